// round 1
// baseline (speedup 1.0000x reference)
#include <cuda_runtime.h>
#include <cuda_bf16.h>
#include <cstdint>

// ---------------------------------------------------------------------------
// AdaptiveLogits: adaptive softmax head
//   head = hidden @ [embed[0:2000]; tail_vec_W]^T + [shortlist_bias; tail_vec_b]
//   dec0 = embed[2000:20000] @ down0_W^T           (18000 x 1024)
//   p0   = hidden[idx0] @ down0_W^T                (n0 x 1024)
//   out0 = p0 @ dec0^T + bias0                     (n0 x 18000)
//   dec1 = embed[20000:50000] @ down1_W^T          (30000 x 256)
//   p1   = hidden[idx1] @ down1_W^T                (n1 x 256)
//   out1 = p1 @ dec1^T + bias1                     (n1 x 30000)
// Output buffer = [head | out0 | out1] flattened.
// ---------------------------------------------------------------------------

#define BATCH 8192
#define HDIM  1024
#define CUT0  2000
#define CUT1  20000
#define CUT2  50000
#define N0MAX BATCH
#define N1MAX BATCH
#define HEAD_N 2002
#define HEAD_ELEMS (8192LL * 2002LL)

// -------------------- device scratch (no allocations allowed) --------------
__device__ __align__(16) float d_dec0[18000 * 1024];
__device__ __align__(16) float d_dec1[30000 * 256];
__device__ __align__(16) float d_p0[BATCH * 1024];
__device__ __align__(16) float d_p1[BATCH * 256];
__device__ int  d_idx0[BATCH];
__device__ int  d_idx1[BATCH];
__device__ int  d_n0;
__device__ int  d_n1;
__device__ long long d_coff1;   // n0 * 18000 (offset of out1 after out0)

// -------------------- setup: cluster membership + stable compaction --------
__global__ void setup_kernel(const void* __restrict__ targets_raw)
{
    __shared__ int s0[1024];
    __shared__ int s1[1024];
    __shared__ int is64_s;

    const int t = threadIdx.x;

    // Sniff targets dtype: int64 values < 2^31 have zero high words.
    if (t == 0) {
        const int* ti = (const int*)targets_raw;
        int allz = 1;
        for (int i = 1; i < 128; i += 2) {
            if (ti[i] != 0) { allz = 0; break; }
        }
        is64_s = allz;
    }
    __syncthreads();
    const bool is64 = (is64_s != 0);

    int cls[8];
    int c0 = 0, c1 = 0;
    #pragma unroll
    for (int i = 0; i < 8; i++) {
        const int idx = t * 8 + i;
        long long v;
        if (is64) v = ((const long long*)targets_raw)[idx];
        else      v = (long long)((const int*)targets_raw)[idx];
        int c = 0;
        if (v >= CUT1)      c = 2;
        else if (v >= CUT0) c = 1;
        cls[i] = c;
        if (c == 1) c0++;
        else if (c == 2) c1++;
    }
    s0[t] = c0;
    s1[t] = c1;
    __syncthreads();

    // Hillis-Steele inclusive scan over 1024 per-thread counts.
    for (int off = 1; off < 1024; off <<= 1) {
        int a0 = (t >= off) ? s0[t - off] : 0;
        int a1 = (t >= off) ? s1[t - off] : 0;
        __syncthreads();
        s0[t] += a0;
        s1[t] += a1;
        __syncthreads();
    }

    int base0 = s0[t] - c0;
    int base1 = s1[t] - c1;
    #pragma unroll
    for (int i = 0; i < 8; i++) {
        const int idx = t * 8 + i;
        if (cls[i] == 1)      d_idx0[base0++] = idx;
        else if (cls[i] == 2) d_idx1[base1++] = idx;
    }

    if (t == 1023) {
        d_n0 = s0[1023];
        d_n1 = s1[1023];
        d_coff1 = (long long)s0[1023] * 18000LL;
    }
}

// -------------------- generic NT SGEMM: C = A * B^T (+bias) ----------------
// A: M x K row-major (optionally row-gathered through gidx)
// B: N x K row-major; if SPLITB, rows >= bsplit come from B2 (row n-bsplit)
// C: M x N with leading dim cld, at Cbase + *coff_dev (or +0)
// M can be dynamic via Mdev (device counter); blocks beyond M exit early.
template <bool GATHER, bool SPLITB>
__global__ void __launch_bounds__(256)
gemm_nt(const float* __restrict__ A,
        const int* __restrict__ gidx,
        const float* __restrict__ B,
        const float* __restrict__ B2, int bsplit,
        const float* __restrict__ bias,
        const float* __restrict__ bias2,
        float* __restrict__ Cbase,
        const long long* __restrict__ coff_dev,
        long long cld,
        int Mstatic, const int* __restrict__ Mdev,
        int N, int K)
{
    const int M = Mdev ? *Mdev : Mstatic;
    const int mBlk = blockIdx.y * 64;
    if (mBlk >= M) return;
    const int nBlk = blockIdx.x * 64;

    __shared__ float As[16][65];
    __shared__ float Bs[16][65];

    const int tid = threadIdx.x;
    const int tx = tid & 15;   // N direction (4 cols each)
    const int ty = tid >> 4;   // M direction (4 rows each)

    // loader mapping: each thread fetches one float4 of A and one of B per k-tile
    const int lrow = tid >> 2;         // 0..63
    const int lk4  = (tid & 3) << 2;   // 0,4,8,12

    const int am = mBlk + lrow;
    const bool avalid = (am < M);
    long long arow = 0;
    if (avalid) {
        const long long r = GATHER ? (long long)gidx[am] : (long long)am;
        arow = r * (long long)K;
    }

    const int bn = nBlk + lrow;
    const bool bvalid = (bn < N);
    const float* bptr = B;   // dummy; guarded by bvalid
    if (bvalid) {
        if (SPLITB && bn >= bsplit) bptr = B2 + (long long)(bn - bsplit) * K;
        else                        bptr = B + (long long)bn * K;
    }

    float acc[4][4] = {};

    for (int k0 = 0; k0 < K; k0 += 16) {
        float4 av = avalid ? *(const float4*)(A + arow + k0 + lk4)
                           : make_float4(0.f, 0.f, 0.f, 0.f);
        float4 bv = bvalid ? *(const float4*)(bptr + k0 + lk4)
                           : make_float4(0.f, 0.f, 0.f, 0.f);
        As[lk4 + 0][lrow] = av.x;
        As[lk4 + 1][lrow] = av.y;
        As[lk4 + 2][lrow] = av.z;
        As[lk4 + 3][lrow] = av.w;
        Bs[lk4 + 0][lrow] = bv.x;
        Bs[lk4 + 1][lrow] = bv.y;
        Bs[lk4 + 2][lrow] = bv.z;
        Bs[lk4 + 3][lrow] = bv.w;
        __syncthreads();

        #pragma unroll
        for (int k = 0; k < 16; k++) {
            float a0 = As[k][ty * 4 + 0];
            float a1 = As[k][ty * 4 + 1];
            float a2 = As[k][ty * 4 + 2];
            float a3 = As[k][ty * 4 + 3];
            float b0 = Bs[k][tx * 4 + 0];
            float b1 = Bs[k][tx * 4 + 1];
            float b2 = Bs[k][tx * 4 + 2];
            float b3 = Bs[k][tx * 4 + 3];
            acc[0][0] += a0 * b0; acc[0][1] += a0 * b1; acc[0][2] += a0 * b2; acc[0][3] += a0 * b3;
            acc[1][0] += a1 * b0; acc[1][1] += a1 * b1; acc[1][2] += a1 * b2; acc[1][3] += a1 * b3;
            acc[2][0] += a2 * b0; acc[2][1] += a2 * b1; acc[2][2] += a2 * b2; acc[2][3] += a2 * b3;
            acc[3][0] += a3 * b0; acc[3][1] += a3 * b1; acc[3][2] += a3 * b2; acc[3][3] += a3 * b3;
        }
        __syncthreads();
    }

    const long long coff = coff_dev ? *coff_dev : 0LL;
    float* C = Cbase + coff;

    #pragma unroll
    for (int i = 0; i < 4; i++) {
        const int m = mBlk + ty * 4 + i;
        if (m >= M) continue;
        #pragma unroll
        for (int j = 0; j < 4; j++) {
            const int n = nBlk + tx * 4 + j;
            if (n >= N) continue;
            float v = acc[i][j];
            if (bias) {
                if (SPLITB && n >= bsplit) v += bias2[n - bsplit];
                else                       v += bias[n];
            }
            C[(long long)m * cld + n] = v;
        }
    }
}

// -------------------- launch --------------------
static inline dim3 grid_for(int n, int m) {
    return dim3((unsigned)((n + 63) / 64), (unsigned)((m + 63) / 64), 1);
}

extern "C" void kernel_launch(void* const* d_in, const int* in_sizes, int n_in,
                              void* d_out, int out_size)
{
    const float* hidden = (const float*)d_in[0];   // 8192 x 1024
    const float* embed  = (const float*)d_in[1];   // 50000 x 1024
    const float* tailW  = (const float*)d_in[2];   // 2 x 1024
    const float* tailb  = (const float*)d_in[3];   // 2
    const float* sbias  = (const float*)d_in[4];   // 2000
    const float* bias0  = (const float*)d_in[5];   // 18000
    const float* bias1  = (const float*)d_in[6];   // 30000
    const float* down0  = (const float*)d_in[7];   // 1024 x 1024
    const float* down1  = (const float*)d_in[8];   // 256 x 1024
    const void*  targs  = d_in[9];                 // 8192 (int64 or int32)
    float* out = (float*)d_out;

    void *p_dec0, *p_dec1, *p_p0, *p_p1, *p_idx0, *p_idx1, *p_n0, *p_n1, *p_coff1;
    cudaGetSymbolAddress(&p_dec0, d_dec0);
    cudaGetSymbolAddress(&p_dec1, d_dec1);
    cudaGetSymbolAddress(&p_p0,   d_p0);
    cudaGetSymbolAddress(&p_p1,   d_p1);
    cudaGetSymbolAddress(&p_idx0, d_idx0);
    cudaGetSymbolAddress(&p_idx1, d_idx1);
    cudaGetSymbolAddress(&p_n0,   d_n0);
    cudaGetSymbolAddress(&p_n1,   d_n1);
    cudaGetSymbolAddress(&p_coff1, d_coff1);

    // 1) cluster membership / compaction / counts / out1 offset
    setup_kernel<<<1, 1024>>>(targs);

    // 2) head = hidden @ [embed[:2000]; tailW]^T + [sbias; tailb]  (8192 x 2002)
    gemm_nt<false, true><<<grid_for(HEAD_N, BATCH), 256>>>(
        hidden, nullptr,
        embed, tailW, CUT0,
        sbias, tailb,
        out, nullptr, (long long)HEAD_N,
        BATCH, nullptr, HEAD_N, HDIM);

    // 3) dec0 = embed[2000:20000] @ down0^T   (18000 x 1024)
    gemm_nt<false, false><<<grid_for(1024, 18000), 256>>>(
        embed + (long long)CUT0 * HDIM, nullptr,
        down0, nullptr, 0,
        nullptr, nullptr,
        (float*)p_dec0, nullptr, 1024LL,
        18000, nullptr, 1024, HDIM);

    // 4) p0 = hidden[idx0] @ down0^T   (n0 x 1024)
    gemm_nt<true, false><<<grid_for(1024, BATCH), 256>>>(
        hidden, (const int*)p_idx0,
        down0, nullptr, 0,
        nullptr, nullptr,
        (float*)p_p0, nullptr, 1024LL,
        0, (const int*)p_n0, 1024, HDIM);

    // 5) out0 = p0 @ dec0^T + bias0   (n0 x 18000) at out + HEAD_ELEMS
    gemm_nt<false, false><<<grid_for(18000, BATCH), 256>>>(
        (const float*)p_p0, nullptr,
        (const float*)p_dec0, nullptr, 0,
        bias0, nullptr,
        out + HEAD_ELEMS, nullptr, 18000LL,
        0, (const int*)p_n0, 18000, 1024);

    // 6) dec1 = embed[20000:50000] @ down1^T   (30000 x 256)
    gemm_nt<false, false><<<grid_for(256, 30000), 256>>>(
        embed + (long long)CUT1 * HDIM, nullptr,
        down1, nullptr, 0,
        nullptr, nullptr,
        (float*)p_dec1, nullptr, 256LL,
        30000, nullptr, 256, HDIM);

    // 7) p1 = hidden[idx1] @ down1^T   (n1 x 256)
    gemm_nt<true, false><<<grid_for(256, BATCH), 256>>>(
        hidden, (const int*)p_idx1,
        down1, nullptr, 0,
        nullptr, nullptr,
        (float*)p_p1, nullptr, 256LL,
        0, (const int*)p_n1, 256, HDIM);

    // 8) out1 = p1 @ dec1^T + bias1   (n1 x 30000) at out + HEAD_ELEMS + n0*18000
    gemm_nt<false, false><<<grid_for(30000, BATCH), 256>>>(
        (const float*)p_p1, nullptr,
        (const float*)p_dec1, nullptr, 0,
        bias1, nullptr,
        out + HEAD_ELEMS, (const long long*)p_coff1, 30000LL,
        0, (const int*)p_n1, 30000, 256);
}

// round 3
// speedup vs baseline: 3.3140x; 3.3140x over previous
#include <cuda_runtime.h>
#include <cuda_bf16.h>
#include <cstdint>

// ---------------------------------------------------------------------------
// AdaptiveLogits via mma.sync.m16n8k16 (bf16, fp32 acc), 3-split precision:
//   C = Ahi*Bhi + Ahi*Blo + Alo*Bhi   (hi = bf16(x), lo = bf16(x - hi))
// Tiles: 128x128x32, 256 threads, cp.async double buffer, ldmatrix fragments.
// (tcgen05 PTX is rejected by this harness's compute_103 virtual target.)
// ---------------------------------------------------------------------------

#define BATCH 8192
#define HDIM  1024
#define CUT0  2000
#define CUT1  20000
#define HEAD_N 2002
#define HEAD_NP 2048
#define HEAD_ELEMS (8192LL*2002LL)
#define DEC0_M 18000
#define DEC1_M 30000
#define DEC0_ROWS 18176   // ceil(18000/128)*128 = 18048, pad a bit more
#define DEC1_ROWS 30208
#define E_ROWS  50176

// -------------------- device scratch (zero-init; no allocs allowed) --------
__device__ __align__(256) __nv_bfloat16 g_h_hi [BATCH*HDIM];
__device__ __align__(256) __nv_bfloat16 g_h_lo [BATCH*HDIM];
__device__ __align__(256) __nv_bfloat16 g_e_hi [E_ROWS*HDIM];
__device__ __align__(256) __nv_bfloat16 g_e_lo [E_ROWS*HDIM];
__device__ __align__(256) __nv_bfloat16 g_hb_hi[HEAD_NP*HDIM];
__device__ __align__(256) __nv_bfloat16 g_hb_lo[HEAD_NP*HDIM];
__device__ __align__(256) float         g_hbias[HEAD_NP];
__device__ __align__(256) __nv_bfloat16 g_d0_hi[1024*HDIM];
__device__ __align__(256) __nv_bfloat16 g_d0_lo[1024*HDIM];
__device__ __align__(256) __nv_bfloat16 g_d1_hi[256*HDIM];
__device__ __align__(256) __nv_bfloat16 g_d1_lo[256*HDIM];
__device__ __align__(256) __nv_bfloat16 g_g0_hi[BATCH*HDIM];
__device__ __align__(256) __nv_bfloat16 g_g0_lo[BATCH*HDIM];
__device__ __align__(256) __nv_bfloat16 g_g1_hi[BATCH*HDIM];
__device__ __align__(256) __nv_bfloat16 g_g1_lo[BATCH*HDIM];
__device__ __align__(256) __nv_bfloat16 g_dec0_hi[DEC0_ROWS*HDIM];
__device__ __align__(256) __nv_bfloat16 g_dec0_lo[DEC0_ROWS*HDIM];
__device__ __align__(256) __nv_bfloat16 g_dec1_hi[DEC1_ROWS*256];
__device__ __align__(256) __nv_bfloat16 g_dec1_lo[DEC1_ROWS*256];
__device__ __align__(256) __nv_bfloat16 g_p0_hi[BATCH*HDIM];
__device__ __align__(256) __nv_bfloat16 g_p0_lo[BATCH*HDIM];
__device__ __align__(256) __nv_bfloat16 g_p1_hi[BATCH*256];
__device__ __align__(256) __nv_bfloat16 g_p1_lo[BATCH*256];
__device__ int  d_idx0[BATCH];
__device__ int  d_idx1[BATCH];
__device__ int  d_n0;
__device__ int  d_n1;
__device__ long long d_coff1;

// -------------------- PTX helpers --------------------
__device__ __forceinline__ uint32_t smem_u32(const void* p) {
    return (uint32_t)__cvta_generic_to_shared(p);
}
__device__ __forceinline__ void cp16(uint32_t dst, const void* src) {
    asm volatile("cp.async.cg.shared.global [%0], [%1], 16;" :: "r"(dst), "l"(src) : "memory");
}
__device__ __forceinline__ void ldm4(uint32_t* r, uint32_t addr) {
    asm volatile("ldmatrix.sync.aligned.m8n8.x4.shared.b16 {%0,%1,%2,%3}, [%4];"
                 : "=r"(r[0]), "=r"(r[1]), "=r"(r[2]), "=r"(r[3]) : "r"(addr));
}
__device__ __forceinline__ void mma16816(float* c, const uint32_t* a, const uint32_t* b) {
    asm volatile(
        "mma.sync.aligned.m16n8k16.row.col.f32.bf16.bf16.f32 "
        "{%0,%1,%2,%3}, {%4,%5,%6,%7}, {%8,%9}, {%0,%1,%2,%3};"
        : "+f"(c[0]), "+f"(c[1]), "+f"(c[2]), "+f"(c[3])
        : "r"(a[0]), "r"(a[1]), "r"(a[2]), "r"(a[3]), "r"(b[0]), "r"(b[1]));
}

// -------------------- smem tile geometry --------------------
#define ROWB 80                   // 32 bf16 (64B) padded to 80B: conflict-free ldmatrix
#define MAT_BYTES (128*ROWB)      // 10240
#define ST_BYTES  (4*MAT_BYTES)   // Ahi,Alo,Bhi,Blo = 40960
#define SMEM_BYTES (2*ST_BYTES)   // 81920

__device__ __forceinline__ void load_stage(
    uint32_t s,
    const char* Ahi, const char* Alo, long long aRB, int aRow0,
    const char* Bhi, const char* Blo, long long bRB, int bRow0,
    long long kByte, int tid)
{
    #pragma unroll
    for (int i = 0; i < 2; i++) {
        const int u = tid + i * 256;        // 0..511
        const int row = u >> 2;             // 0..127
        const int ch  = u & 3;              // 16B chunk
        const uint32_t d = (uint32_t)(row * ROWB + ch * 16);
        const long long ga = (long long)(aRow0 + row) * aRB + kByte + ch * 16;
        const long long gb = (long long)(bRow0 + row) * bRB + kByte + ch * 16;
        cp16(s + 0 * MAT_BYTES + d, Ahi + ga);
        cp16(s + 1 * MAT_BYTES + d, Alo + ga);
        cp16(s + 2 * MAT_BYTES + d, Bhi + gb);
        cp16(s + 3 * MAT_BYTES + d, Blo + gb);
    }
}

// -------------------- GEMM: C = A * B^T (3-split bf16) ---------------------
// OUTMODE 0: fp32 out (+bias, +*coff)   OUTMODE 1: bf16 hi/lo split pair out
template <int OUTMODE>
__global__ void __launch_bounds__(256, 1)
mm_gemm(const __nv_bfloat16* __restrict__ Ahi_, const __nv_bfloat16* __restrict__ Alo_,
        const __nv_bfloat16* __restrict__ Bhi_, const __nv_bfloat16* __restrict__ Blo_,
        int K, int N, int Mstatic, const int* __restrict__ Mdev,
        float* __restrict__ Cf, const float* __restrict__ bias,
        long long cld, const long long* __restrict__ coff,
        __nv_bfloat16* __restrict__ Chi, __nv_bfloat16* __restrict__ Clo)
{
    const int M = Mdev ? *Mdev : Mstatic;
    const int mBlk = blockIdx.y * 128;
    if (mBlk >= M) return;
    const int nBlk = blockIdx.x * 128;

    extern __shared__ __align__(1024) char smem[];
    const uint32_t sb = smem_u32(smem);
    const int tid = threadIdx.x;
    const int lane = tid & 31;
    const int wid = tid >> 5;
    const int wm = (wid & 1) * 64;    // warp M offset
    const int wn = (wid >> 1) * 32;   // warp N offset

    const char* Ahi = (const char*)Ahi_;
    const char* Alo = (const char*)Alo_;
    const char* Bhi = (const char*)Bhi_;
    const char* Blo = (const char*)Blo_;
    const long long aRB = (long long)K * 2;
    const long long bRB = (long long)K * 2;
    const int nk = K >> 5;            // BK = 32

    float acc[4][4][4];
    #pragma unroll
    for (int i = 0; i < 4; i++)
        #pragma unroll
        for (int j = 0; j < 4; j++)
            #pragma unroll
            for (int k = 0; k < 4; k++) acc[i][j][k] = 0.f;

    // per-lane ldmatrix address components (byte offsets within a matrix)
    const uint32_t aRowOff = (uint32_t)((wm + (lane & 15)) * ROWB);
    const uint32_t aColOff = (uint32_t)((lane >> 4) * 16);          // halves*2
    const uint32_t bRowOff = (uint32_t)((wn + ((lane >> 4) & 1) * 8 + (lane & 7)) * ROWB);
    const uint32_t bColOff = (uint32_t)(((lane >> 3) & 1) * 16);

    load_stage(sb, Ahi, Alo, aRB, mBlk, Bhi, Blo, bRB, nBlk, 0, tid);
    asm volatile("cp.async.commit_group;" ::: "memory");

    for (int c = 0; c < nk; c++) {
        asm volatile("cp.async.wait_group 0;" ::: "memory");
        __syncthreads();
        if (c + 1 < nk) {
            load_stage(sb + ((c + 1) & 1) * ST_BYTES,
                       Ahi, Alo, aRB, mBlk, Bhi, Blo, bRB, nBlk,
                       (long long)(c + 1) * 64, tid);
            asm volatile("cp.async.commit_group;" ::: "memory");
        }
        const uint32_t st = sb + (uint32_t)(c & 1) * ST_BYTES;

        #pragma unroll
        for (int k16 = 0; k16 < 2; k16++) {
            uint32_t ahi[4][4], alo[4][4], bhi[2][4], blo[2][4];
            const uint32_t ak = (uint32_t)(k16 * 32) + aColOff;
            const uint32_t bk = (uint32_t)(k16 * 32) + bColOff;
            #pragma unroll
            for (int mt = 0; mt < 4; mt++) {
                const uint32_t ad = st + aRowOff + (uint32_t)(mt * 16 * ROWB) + ak;
                ldm4(ahi[mt], ad);
                ldm4(alo[mt], ad + MAT_BYTES);
            }
            #pragma unroll
            for (int g = 0; g < 2; g++) {
                const uint32_t bd = st + 2 * MAT_BYTES + bRowOff
                                  + (uint32_t)(g * 16 * ROWB) + bk;
                ldm4(bhi[g], bd);
                ldm4(blo[g], bd + MAT_BYTES);
            }
            #pragma unroll
            for (int mt = 0; mt < 4; mt++) {
                #pragma unroll
                for (int nt = 0; nt < 4; nt++) {
                    const uint32_t* bh = &bhi[nt >> 1][(nt & 1) * 2];
                    const uint32_t* bl = &blo[nt >> 1][(nt & 1) * 2];
                    mma16816(acc[mt][nt], ahi[mt], bh);
                    mma16816(acc[mt][nt], ahi[mt], bl);
                    mma16816(acc[mt][nt], alo[mt], bh);
                }
            }
        }
    }

    // -------- epilogue: direct global stores (32B-contiguous per quad) --------
    const long long cOff = (OUTMODE == 0 && coff) ? *coff : 0LL;
    const int r = lane >> 2;
    const int cq = (lane & 3) * 2;

    #pragma unroll
    for (int mt = 0; mt < 4; mt++) {
        #pragma unroll
        for (int nt = 0; nt < 4; nt++) {
            const int m0 = mBlk + wm + mt * 16 + r;
            const int n  = nBlk + wn + nt * 8 + cq;
            if (n >= N) continue;
            const float* a4 = acc[mt][nt];
            if (OUTMODE == 0) {
                const float b0 = bias[n], b1 = bias[n + 1];
                if (m0 < M) {
                    float2 v = make_float2(a4[0] + b0, a4[1] + b1);
                    *(float2*)(Cf + cOff + (long long)m0 * cld + n) = v;
                }
                if (m0 + 8 < M) {
                    float2 v = make_float2(a4[2] + b0, a4[3] + b1);
                    *(float2*)(Cf + cOff + (long long)(m0 + 8) * cld + n) = v;
                }
            } else {
                if (m0 < M) {
                    __nv_bfloat16 h0 = __float2bfloat16(a4[0]);
                    __nv_bfloat16 h1 = __float2bfloat16(a4[1]);
                    *(__nv_bfloat162*)(Chi + (long long)m0 * cld + n) = __halves2bfloat162(h0, h1);
                    *(__nv_bfloat162*)(Clo + (long long)m0 * cld + n) = __halves2bfloat162(
                        __float2bfloat16(a4[0] - __bfloat162float(h0)),
                        __float2bfloat16(a4[1] - __bfloat162float(h1)));
                }
                if (m0 + 8 < M) {
                    __nv_bfloat16 h2 = __float2bfloat16(a4[2]);
                    __nv_bfloat16 h3 = __float2bfloat16(a4[3]);
                    *(__nv_bfloat162*)(Chi + (long long)(m0 + 8) * cld + n) = __halves2bfloat162(h2, h3);
                    *(__nv_bfloat162*)(Clo + (long long)(m0 + 8) * cld + n) = __halves2bfloat162(
                        __float2bfloat16(a4[2] - __bfloat162float(h2)),
                        __float2bfloat16(a4[3] - __bfloat162float(h3)));
                }
            }
        }
    }
}

// -------------------- setup: compaction --------------------
__global__ void setup_kernel(const void* __restrict__ targets_raw)
{
    __shared__ int s0[1024];
    __shared__ int s1[1024];
    __shared__ int is64_s;
    const int t = threadIdx.x;
    if (t == 0) {
        const int* ti = (const int*)targets_raw;
        int allz = 1;
        for (int i = 1; i < 128; i += 2) if (ti[i] != 0) { allz = 0; break; }
        is64_s = allz;
    }
    __syncthreads();
    const bool is64 = (is64_s != 0);

    int cls[8]; int c0 = 0, c1 = 0;
    #pragma unroll
    for (int i = 0; i < 8; i++) {
        const int idx = t * 8 + i;
        long long v = is64 ? ((const long long*)targets_raw)[idx]
                           : (long long)((const int*)targets_raw)[idx];
        int c = 0;
        if (v >= CUT1) c = 2; else if (v >= CUT0) c = 1;
        cls[i] = c;
        if (c == 1) c0++; else if (c == 2) c1++;
    }
    s0[t] = c0; s1[t] = c1;
    __syncthreads();
    for (int off = 1; off < 1024; off <<= 1) {
        int a0 = (t >= off) ? s0[t - off] : 0;
        int a1 = (t >= off) ? s1[t - off] : 0;
        __syncthreads();
        s0[t] += a0; s1[t] += a1;
        __syncthreads();
    }
    int b0 = s0[t] - c0, b1 = s1[t] - c1;
    #pragma unroll
    for (int i = 0; i < 8; i++) {
        const int idx = t * 8 + i;
        if (cls[i] == 1)      d_idx0[b0++] = idx;
        else if (cls[i] == 2) d_idx1[b1++] = idx;
    }
    if (t == 1023) {
        d_n0 = s0[1023];
        d_n1 = s1[1023];
        d_coff1 = (long long)s0[1023] * 18000LL;
    }
}

// -------------------- fp32 -> bf16 hi/lo split --------------------
__global__ void split_kernel(const float4* __restrict__ src,
                             __nv_bfloat162* __restrict__ hi,
                             __nv_bfloat162* __restrict__ lo, long long n4)
{
    long long i = blockIdx.x * (long long)blockDim.x + threadIdx.x;
    const long long stride = gridDim.x * (long long)blockDim.x;
    for (; i < n4; i += stride) {
        float4 v = src[i];
        __nv_bfloat16 h0 = __float2bfloat16(v.x);
        __nv_bfloat16 h1 = __float2bfloat16(v.y);
        __nv_bfloat16 h2 = __float2bfloat16(v.z);
        __nv_bfloat16 h3 = __float2bfloat16(v.w);
        hi[i*2+0] = __halves2bfloat162(h0, h1);
        hi[i*2+1] = __halves2bfloat162(h2, h3);
        lo[i*2+0] = __halves2bfloat162(__float2bfloat16(v.x - __bfloat162float(h0)),
                                       __float2bfloat16(v.y - __bfloat162float(h1)));
        lo[i*2+1] = __halves2bfloat162(__float2bfloat16(v.z - __bfloat162float(h2)),
                                       __float2bfloat16(v.w - __bfloat162float(h3)));
    }
}

// -------------------- head B pack (embed[:2000] ++ tailW) ------------------
__global__ void pack_head_rows(const __nv_bfloat16* __restrict__ ehi,
                               const __nv_bfloat16* __restrict__ elo,
                               const float* __restrict__ tailW)
{
    const int row = blockIdx.x;       // 0..2001
    const int t = threadIdx.x;
    if (row < CUT0) {
        const uint4* sh = (const uint4*)(ehi + (long long)row * HDIM);
        const uint4* sl = (const uint4*)(elo + (long long)row * HDIM);
        uint4* dh = (uint4*)(g_hb_hi + (long long)row * HDIM);
        uint4* dl = (uint4*)(g_hb_lo + (long long)row * HDIM);
        for (int i = t; i < HDIM / 8; i += blockDim.x) { dh[i] = sh[i]; dl[i] = sl[i]; }
    } else {
        const float* src = tailW + (long long)(row - CUT0) * HDIM;
        __nv_bfloat16* dh = g_hb_hi + (long long)row * HDIM;
        __nv_bfloat16* dl = g_hb_lo + (long long)row * HDIM;
        for (int i = t; i < HDIM; i += blockDim.x) {
            float x = src[i];
            __nv_bfloat16 h = __float2bfloat16(x);
            dh[i] = h;
            dl[i] = __float2bfloat16(x - __bfloat162float(h));
        }
    }
}
__global__ void pack_head_bias(const float* __restrict__ sbias,
                               const float* __restrict__ tailb)
{
    const int i = blockIdx.x * blockDim.x + threadIdx.x;
    if (i < HEAD_NP)
        g_hbias[i] = (i < CUT0) ? sbias[i] : ((i < HEAD_N) ? tailb[i - CUT0] : 0.f);
}

// -------------------- gather compacted hidden rows --------------------
__global__ void gather_rows(const __nv_bfloat16* __restrict__ hhi,
                            const __nv_bfloat16* __restrict__ hlo,
                            const int* __restrict__ idx, const int* __restrict__ n,
                            __nv_bfloat16* __restrict__ ghi, __nv_bfloat16* __restrict__ glo)
{
    const int b = blockIdx.x;
    if (b >= *n) return;
    const int r = idx[b];
    const uint4* sh = (const uint4*)(hhi + (long long)r * HDIM);
    const uint4* sl = (const uint4*)(hlo + (long long)r * HDIM);
    uint4* dh = (uint4*)(ghi + (long long)b * HDIM);
    uint4* dl = (uint4*)(glo + (long long)b * HDIM);
    for (int i = threadIdx.x; i < HDIM / 8; i += blockDim.x) { dh[i] = sh[i]; dl[i] = sl[i]; }
}

// -------------------- host launch --------------------
extern "C" void kernel_launch(void* const* d_in, const int* in_sizes, int n_in,
                              void* d_out, int out_size)
{
    const float* hidden = (const float*)d_in[0];
    const float* embed  = (const float*)d_in[1];
    const float* tailW  = (const float*)d_in[2];
    const float* tailb  = (const float*)d_in[3];
    const float* sbias  = (const float*)d_in[4];
    const float* bias0  = (const float*)d_in[5];
    const float* bias1  = (const float*)d_in[6];
    const float* down0  = (const float*)d_in[7];
    const float* down1  = (const float*)d_in[8];
    const void*  targs  = d_in[9];
    float* out = (float*)d_out;

    #define SYM(p, s) void* p; cudaGetSymbolAddress(&p, s)
    SYM(p_hhi, g_h_hi);  SYM(p_hlo, g_h_lo);
    SYM(p_ehi, g_e_hi);  SYM(p_elo, g_e_lo);
    SYM(p_hbh, g_hb_hi); SYM(p_hbl, g_hb_lo); SYM(p_hbias, g_hbias);
    SYM(p_d0h, g_d0_hi); SYM(p_d0l, g_d0_lo);
    SYM(p_d1h, g_d1_hi); SYM(p_d1l, g_d1_lo);
    SYM(p_g0h, g_g0_hi); SYM(p_g0l, g_g0_lo);
    SYM(p_g1h, g_g1_hi); SYM(p_g1l, g_g1_lo);
    SYM(p_dc0h, g_dec0_hi); SYM(p_dc0l, g_dec0_lo);
    SYM(p_dc1h, g_dec1_hi); SYM(p_dc1l, g_dec1_lo);
    SYM(p_p0h, g_p0_hi); SYM(p_p0l, g_p0_lo);
    SYM(p_p1h, g_p1_hi); SYM(p_p1l, g_p1_lo);
    SYM(p_i0, d_idx0);   SYM(p_i1, d_idx1);
    SYM(p_n0, d_n0);     SYM(p_n1, d_n1);   SYM(p_c1, d_coff1);
    #undef SYM

    cudaFuncSetAttribute(mm_gemm<0>, cudaFuncAttributeMaxDynamicSharedMemorySize, SMEM_BYTES);
    cudaFuncSetAttribute(mm_gemm<1>, cudaFuncAttributeMaxDynamicSharedMemorySize, SMEM_BYTES);

    // setup + operand conversion
    setup_kernel<<<1, 1024>>>(targs);
    split_kernel<<<4096, 256>>>((const float4*)hidden, (__nv_bfloat162*)p_hhi,
                                (__nv_bfloat162*)p_hlo, (long long)BATCH * HDIM / 4);
    split_kernel<<<16384, 256>>>((const float4*)embed, (__nv_bfloat162*)p_ehi,
                                 (__nv_bfloat162*)p_elo, 50000LL * HDIM / 4);
    split_kernel<<<1024, 256>>>((const float4*)down0, (__nv_bfloat162*)p_d0h,
                                (__nv_bfloat162*)p_d0l, 1024LL * HDIM / 4);
    split_kernel<<<256, 256>>>((const float4*)down1, (__nv_bfloat162*)p_d1h,
                               (__nv_bfloat162*)p_d1l, 256LL * HDIM / 4);
    pack_head_rows<<<HEAD_N, 256>>>((const __nv_bfloat16*)p_ehi,
                                    (const __nv_bfloat16*)p_elo, tailW);
    pack_head_bias<<<8, 256>>>(sbias, tailb);
    gather_rows<<<BATCH, 128>>>((const __nv_bfloat16*)p_hhi, (const __nv_bfloat16*)p_hlo,
                                (const int*)p_i0, (const int*)p_n0,
                                (__nv_bfloat16*)p_g0h, (__nv_bfloat16*)p_g0l);
    gather_rows<<<BATCH, 128>>>((const __nv_bfloat16*)p_hhi, (const __nv_bfloat16*)p_hlo,
                                (const int*)p_i1, (const int*)p_n1,
                                (__nv_bfloat16*)p_g1h, (__nv_bfloat16*)p_g1l);

    #define BF(p) (const __nv_bfloat16*)(p)
    // head: [8192 x 2002] = hidden @ hb^T + hbias
    mm_gemm<0><<<dim3(16, 64), 256, SMEM_BYTES>>>(
        BF(p_hhi), BF(p_hlo), BF(p_hbh), BF(p_hbl),
        HDIM, HEAD_N, BATCH, nullptr,
        out, (const float*)p_hbias, (long long)HEAD_N, nullptr, nullptr, nullptr);

    // dec0: [18000 x 1024] = embed[2000:20000] @ down0^T -> bf16 split
    mm_gemm<1><<<dim3(8, 141), 256, SMEM_BYTES>>>(
        BF(p_ehi) + (long long)CUT0 * HDIM, BF(p_elo) + (long long)CUT0 * HDIM,
        BF(p_d0h), BF(p_d0l),
        HDIM, 1024, DEC0_M, nullptr,
        nullptr, nullptr, 1024LL, nullptr, (__nv_bfloat16*)p_dc0h, (__nv_bfloat16*)p_dc0l);

    // p0: [n0 x 1024] = g0 @ down0^T -> bf16 split
    mm_gemm<1><<<dim3(8, 64), 256, SMEM_BYTES>>>(
        BF(p_g0h), BF(p_g0l), BF(p_d0h), BF(p_d0l),
        HDIM, 1024, 0, (const int*)p_n0,
        nullptr, nullptr, 1024LL, nullptr, (__nv_bfloat16*)p_p0h, (__nv_bfloat16*)p_p0l);

    // out0: [n0 x 18000] = p0 @ dec0^T + bias0
    mm_gemm<0><<<dim3(141, 64), 256, SMEM_BYTES>>>(
        BF(p_p0h), BF(p_p0l), BF(p_dc0h), BF(p_dc0l),
        HDIM, DEC0_M, 0, (const int*)p_n0,
        out + HEAD_ELEMS, bias0, 18000LL, nullptr, nullptr, nullptr);

    // dec1: [30000 x 256] = embed[20000:50000] @ down1^T -> bf16 split
    mm_gemm<1><<<dim3(2, 235), 256, SMEM_BYTES>>>(
        BF(p_ehi) + (long long)CUT1 * HDIM, BF(p_elo) + (long long)CUT1 * HDIM,
        BF(p_d1h), BF(p_d1l),
        HDIM, 256, DEC1_M, nullptr,
        nullptr, nullptr, 256LL, nullptr, (__nv_bfloat16*)p_dc1h, (__nv_bfloat16*)p_dc1l);

    // p1: [n1 x 256] = g1 @ down1^T -> bf16 split
    mm_gemm<1><<<dim3(2, 64), 256, SMEM_BYTES>>>(
        BF(p_g1h), BF(p_g1l), BF(p_d1h), BF(p_d1l),
        HDIM, 256, 0, (const int*)p_n1,
        nullptr, nullptr, 256LL, nullptr, (__nv_bfloat16*)p_p1h, (__nv_bfloat16*)p_p1l);

    // out1: [n1 x 30000] = p1 @ dec1^T + bias1  (K = 256)
    mm_gemm<0><<<dim3(235, 64), 256, SMEM_BYTES>>>(
        BF(p_p1h), BF(p_p1l), BF(p_dc1h), BF(p_dc1l),
        256, DEC1_M, 0, (const int*)p_n1,
        out + HEAD_ELEMS, bias1, 30000LL, (const long long*)p_c1, nullptr, nullptr);
    #undef BF
}

// round 4
// speedup vs baseline: 6.1992x; 1.8706x over previous
#include <cuda_runtime.h>
#include <cuda_bf16.h>
#include <cuda_fp16.h>
#include <cstdint>

// ---------------------------------------------------------------------------
// AdaptiveLogits, mixed precision on mma.sync tensor cores:
//   intermediate GEMMs (dec0,p0,dec1,p1): bf16 3-split (err ~2^-17) -> fp16
//   output GEMMs (head,out0,out1): single-pass fp16 (err ~4e-4 < 1e-3)
// ---------------------------------------------------------------------------

#define BATCH 8192
#define HDIM  1024
#define CUT0  2000
#define CUT1  20000
#define HEAD_N 2002
#define HEAD_NP 2048
#define HEAD_ELEMS (8192LL*2002LL)
#define DEC0_M 18000
#define DEC1_M 30000
#define DEC0_ROWS 18176
#define DEC1_ROWS 30208
#define E_ROWS  50176

// -------------------- device scratch (zero-init; no allocs allowed) --------
__device__ __align__(256) __nv_bfloat16 g_h_hi [BATCH*HDIM];
__device__ __align__(256) __nv_bfloat16 g_h_lo [BATCH*HDIM];
__device__ __align__(256) __nv_bfloat16 g_e_hi [E_ROWS*HDIM];
__device__ __align__(256) __nv_bfloat16 g_e_lo [E_ROWS*HDIM];
__device__ __align__(256) __nv_bfloat16 g_d0_hi[1024*HDIM];
__device__ __align__(256) __nv_bfloat16 g_d0_lo[1024*HDIM];
__device__ __align__(256) __nv_bfloat16 g_d1_hi[256*HDIM];
__device__ __align__(256) __nv_bfloat16 g_d1_lo[256*HDIM];
__device__ __align__(256) __nv_bfloat16 g_g0_hi[BATCH*HDIM];
__device__ __align__(256) __nv_bfloat16 g_g0_lo[BATCH*HDIM];
__device__ __align__(256) __nv_bfloat16 g_g1_hi[BATCH*HDIM];
__device__ __align__(256) __nv_bfloat16 g_g1_lo[BATCH*HDIM];
__device__ __align__(256) __half g_h16   [BATCH*HDIM];          // hidden fp16
__device__ __align__(256) __half g_hb16  [HEAD_NP*HDIM];        // head B fp16
__device__ __align__(256) float  g_hbias [HEAD_NP];
__device__ __align__(256) __half g_dec0h [DEC0_ROWS*HDIM];
__device__ __align__(256) __half g_dec1h [DEC1_ROWS*256];
__device__ __align__(256) __half g_p0h   [BATCH*HDIM];
__device__ __align__(256) __half g_p1h   [BATCH*256];
__device__ int  d_idx0[BATCH];
__device__ int  d_idx1[BATCH];
__device__ int  d_n0;
__device__ int  d_n1;
__device__ long long d_coff1;

// -------------------- PTX helpers --------------------
__device__ __forceinline__ uint32_t smem_u32(const void* p) {
    return (uint32_t)__cvta_generic_to_shared(p);
}
__device__ __forceinline__ void cp16(uint32_t dst, const void* src) {
    asm volatile("cp.async.cg.shared.global [%0], [%1], 16;" :: "r"(dst), "l"(src) : "memory");
}
__device__ __forceinline__ void ldm4(uint32_t* r, uint32_t addr) {
    asm volatile("ldmatrix.sync.aligned.m8n8.x4.shared.b16 {%0,%1,%2,%3}, [%4];"
                 : "=r"(r[0]), "=r"(r[1]), "=r"(r[2]), "=r"(r[3]) : "r"(addr));
}
__device__ __forceinline__ void mma_bf16(float* c, const uint32_t* a, const uint32_t* b) {
    asm volatile(
        "mma.sync.aligned.m16n8k16.row.col.f32.bf16.bf16.f32 "
        "{%0,%1,%2,%3}, {%4,%5,%6,%7}, {%8,%9}, {%0,%1,%2,%3};"
        : "+f"(c[0]), "+f"(c[1]), "+f"(c[2]), "+f"(c[3])
        : "r"(a[0]), "r"(a[1]), "r"(a[2]), "r"(a[3]), "r"(b[0]), "r"(b[1]));
}
__device__ __forceinline__ void mma_f16(float* c, const uint32_t* a, const uint32_t* b) {
    asm volatile(
        "mma.sync.aligned.m16n8k16.row.col.f32.f16.f16.f32 "
        "{%0,%1,%2,%3}, {%4,%5,%6,%7}, {%8,%9}, {%0,%1,%2,%3};"
        : "+f"(c[0]), "+f"(c[1]), "+f"(c[2]), "+f"(c[3])
        : "r"(a[0]), "r"(a[1]), "r"(a[2]), "r"(a[3]), "r"(b[0]), "r"(b[1]));
}

// -------------------- shared tile geometry --------------------
#define ROWB 80                    // 32 halfwords padded to 80B (conflict-free)
#define MAT_BYTES (128*ROWB)       // 10240

// =====================  Kernel A: bf16 3-split -> fp16  =====================
#define A_ST (4*MAT_BYTES)         // Ahi,Alo,Bhi,Blo
#define A_SMEM (2*A_ST)            // 81920

__device__ __forceinline__ void load_stage4(
    uint32_t s,
    const char* Ahi, const char* Alo, long long aRB, int aRow0,
    const char* Bhi, const char* Blo, long long bRB, int bRow0,
    long long kByte, int tid)
{
    #pragma unroll
    for (int i = 0; i < 2; i++) {
        const int u = tid + i * 256;
        const int row = u >> 2;
        const int ch  = u & 3;
        const uint32_t d = (uint32_t)(row * ROWB + ch * 16);
        const long long ga = (long long)(aRow0 + row) * aRB + kByte + ch * 16;
        const long long gb = (long long)(bRow0 + row) * bRB + kByte + ch * 16;
        cp16(s + 0 * MAT_BYTES + d, Ahi + ga);
        cp16(s + 1 * MAT_BYTES + d, Alo + ga);
        cp16(s + 2 * MAT_BYTES + d, Bhi + gb);
        cp16(s + 3 * MAT_BYTES + d, Blo + gb);
    }
}

__global__ void __launch_bounds__(256, 1)
gemm3(const __nv_bfloat16* __restrict__ Ahi_, const __nv_bfloat16* __restrict__ Alo_,
      const __nv_bfloat16* __restrict__ Bhi_, const __nv_bfloat16* __restrict__ Blo_,
      int K, int N, int Mstatic, const int* __restrict__ Mdev,
      __half* __restrict__ Ch, long long cld)
{
    const int M = Mdev ? *Mdev : Mstatic;
    const int mBlk = blockIdx.y * 128;
    if (mBlk >= M) return;
    const int nBlk = blockIdx.x * 128;

    extern __shared__ __align__(1024) char smem[];
    const uint32_t sb = smem_u32(smem);
    const int tid = threadIdx.x;
    const int lane = tid & 31;
    const int wid = tid >> 5;
    const int wm = (wid & 1) * 64;
    const int wn = (wid >> 1) * 32;

    const char* Ahi = (const char*)Ahi_;
    const char* Alo = (const char*)Alo_;
    const char* Bhi = (const char*)Bhi_;
    const char* Blo = (const char*)Blo_;
    const long long aRB = (long long)K * 2;
    const long long bRB = (long long)K * 2;
    const int nk = K >> 5;

    float acc[4][4][4];
    #pragma unroll
    for (int i = 0; i < 4; i++)
        #pragma unroll
        for (int j = 0; j < 4; j++)
            #pragma unroll
            for (int k = 0; k < 4; k++) acc[i][j][k] = 0.f;

    const uint32_t aRowOff = (uint32_t)((wm + (lane & 15)) * ROWB);
    const uint32_t aColOff = (uint32_t)((lane >> 4) * 16);
    const uint32_t bRowOff = (uint32_t)((wn + ((lane >> 4) & 1) * 8 + (lane & 7)) * ROWB);
    const uint32_t bColOff = (uint32_t)(((lane >> 3) & 1) * 16);

    load_stage4(sb, Ahi, Alo, aRB, mBlk, Bhi, Blo, bRB, nBlk, 0, tid);
    asm volatile("cp.async.commit_group;" ::: "memory");

    for (int c = 0; c < nk; c++) {
        asm volatile("cp.async.wait_group 0;" ::: "memory");
        __syncthreads();
        if (c + 1 < nk) {
            load_stage4(sb + ((c + 1) & 1) * A_ST,
                        Ahi, Alo, aRB, mBlk, Bhi, Blo, bRB, nBlk,
                        (long long)(c + 1) * 64, tid);
            asm volatile("cp.async.commit_group;" ::: "memory");
        }
        const uint32_t st = sb + (uint32_t)(c & 1) * A_ST;

        #pragma unroll
        for (int k16 = 0; k16 < 2; k16++) {
            uint32_t ahi[4][4], alo[4][4], bhi[2][4], blo[2][4];
            const uint32_t ak = (uint32_t)(k16 * 32) + aColOff;
            const uint32_t bk = (uint32_t)(k16 * 32) + bColOff;
            #pragma unroll
            for (int mt = 0; mt < 4; mt++) {
                const uint32_t ad = st + aRowOff + (uint32_t)(mt * 16 * ROWB) + ak;
                ldm4(ahi[mt], ad);
                ldm4(alo[mt], ad + MAT_BYTES);
            }
            #pragma unroll
            for (int g = 0; g < 2; g++) {
                const uint32_t bd = st + 2 * MAT_BYTES + bRowOff
                                  + (uint32_t)(g * 16 * ROWB) + bk;
                ldm4(bhi[g], bd);
                ldm4(blo[g], bd + MAT_BYTES);
            }
            #pragma unroll
            for (int mt = 0; mt < 4; mt++) {
                #pragma unroll
                for (int nt = 0; nt < 4; nt++) {
                    const uint32_t* bh = &bhi[nt >> 1][(nt & 1) * 2];
                    const uint32_t* bl = &blo[nt >> 1][(nt & 1) * 2];
                    mma_bf16(acc[mt][nt], ahi[mt], bh);
                    mma_bf16(acc[mt][nt], ahi[mt], bl);
                    mma_bf16(acc[mt][nt], alo[mt], bh);
                }
            }
        }
    }

    const int r = lane >> 2;
    const int cq = (lane & 3) * 2;
    #pragma unroll
    for (int mt = 0; mt < 4; mt++) {
        #pragma unroll
        for (int nt = 0; nt < 4; nt++) {
            const int m0 = mBlk + wm + mt * 16 + r;
            const int n  = nBlk + wn + nt * 8 + cq;
            if (n >= N) continue;
            const float* a4 = acc[mt][nt];
            if (m0 < M)
                *(__half2*)(Ch + (long long)m0 * cld + n) =
                    __floats2half2_rn(a4[0], a4[1]);
            if (m0 + 8 < M)
                *(__half2*)(Ch + (long long)(m0 + 8) * cld + n) =
                    __floats2half2_rn(a4[2], a4[3]);
        }
    }
}

// =====================  Kernel B: single-pass fp16  =====================
#define B_ST (2*MAT_BYTES)         // Ah,Bh = 20480
#define B_SMEM (2*B_ST)            // 40960

__device__ __forceinline__ void load_stage2(
    uint32_t s,
    const char* Ah, long long aRB, int aRow0,
    const char* Bh, long long bRB, int bRow0,
    long long kByte, int tid)
{
    #pragma unroll
    for (int i = 0; i < 2; i++) {
        const int u = tid + i * 256;
        const int row = u >> 2;
        const int ch  = u & 3;
        const uint32_t d = (uint32_t)(row * ROWB + ch * 16);
        cp16(s + d,             Ah + (long long)(aRow0 + row) * aRB + kByte + ch * 16);
        cp16(s + MAT_BYTES + d, Bh + (long long)(bRow0 + row) * bRB + kByte + ch * 16);
    }
}

__global__ void __launch_bounds__(256, 2)
gemm1(const __half* __restrict__ Ah_, const __half* __restrict__ Bh_,
      int K, int N, int Mstatic, const int* __restrict__ Mdev,
      float* __restrict__ Cf, const float* __restrict__ bias,
      long long cld, const long long* __restrict__ coff)
{
    const int M = Mdev ? *Mdev : Mstatic;
    const int mBlk = blockIdx.y * 128;
    if (mBlk >= M) return;
    const int nBlk = blockIdx.x * 128;

    extern __shared__ __align__(1024) char smem[];
    const uint32_t sb = smem_u32(smem);
    const int tid = threadIdx.x;
    const int lane = tid & 31;
    const int wid = tid >> 5;
    const int wm = (wid & 1) * 64;
    const int wn = (wid >> 1) * 32;

    const char* Ah = (const char*)Ah_;
    const char* Bh = (const char*)Bh_;
    const long long aRB = (long long)K * 2;
    const long long bRB = (long long)K * 2;
    const int nk = K >> 5;

    float acc[4][4][4];
    #pragma unroll
    for (int i = 0; i < 4; i++)
        #pragma unroll
        for (int j = 0; j < 4; j++)
            #pragma unroll
            for (int k = 0; k < 4; k++) acc[i][j][k] = 0.f;

    const uint32_t aRowOff = (uint32_t)((wm + (lane & 15)) * ROWB);
    const uint32_t aColOff = (uint32_t)((lane >> 4) * 16);
    const uint32_t bRowOff = (uint32_t)((wn + ((lane >> 4) & 1) * 8 + (lane & 7)) * ROWB);
    const uint32_t bColOff = (uint32_t)(((lane >> 3) & 1) * 16);

    load_stage2(sb, Ah, aRB, mBlk, Bh, bRB, nBlk, 0, tid);
    asm volatile("cp.async.commit_group;" ::: "memory");

    for (int c = 0; c < nk; c++) {
        asm volatile("cp.async.wait_group 0;" ::: "memory");
        __syncthreads();
        if (c + 1 < nk) {
            load_stage2(sb + ((c + 1) & 1) * B_ST,
                        Ah, aRB, mBlk, Bh, bRB, nBlk,
                        (long long)(c + 1) * 64, tid);
            asm volatile("cp.async.commit_group;" ::: "memory");
        }
        const uint32_t st = sb + (uint32_t)(c & 1) * B_ST;

        #pragma unroll
        for (int k16 = 0; k16 < 2; k16++) {
            uint32_t af[4][4], bf[2][4];
            const uint32_t ak = (uint32_t)(k16 * 32) + aColOff;
            const uint32_t bk = (uint32_t)(k16 * 32) + bColOff;
            #pragma unroll
            for (int mt = 0; mt < 4; mt++)
                ldm4(af[mt], st + aRowOff + (uint32_t)(mt * 16 * ROWB) + ak);
            #pragma unroll
            for (int g = 0; g < 2; g++)
                ldm4(bf[g], st + MAT_BYTES + bRowOff + (uint32_t)(g * 16 * ROWB) + bk);
            #pragma unroll
            for (int mt = 0; mt < 4; mt++)
                #pragma unroll
                for (int nt = 0; nt < 4; nt++)
                    mma_f16(acc[mt][nt], af[mt], &bf[nt >> 1][(nt & 1) * 2]);
        }
    }

    const long long cOff = coff ? *coff : 0LL;
    const int r = lane >> 2;
    const int cq = (lane & 3) * 2;
    #pragma unroll
    for (int mt = 0; mt < 4; mt++) {
        #pragma unroll
        for (int nt = 0; nt < 4; nt++) {
            const int m0 = mBlk + wm + mt * 16 + r;
            const int n  = nBlk + wn + nt * 8 + cq;
            if (n >= N) continue;
            const float* a4 = acc[mt][nt];
            const float b0 = bias[n], b1 = bias[n + 1];
            if (m0 < M)
                *(float2*)(Cf + cOff + (long long)m0 * cld + n) =
                    make_float2(a4[0] + b0, a4[1] + b1);
            if (m0 + 8 < M)
                *(float2*)(Cf + cOff + (long long)(m0 + 8) * cld + n) =
                    make_float2(a4[2] + b0, a4[3] + b1);
        }
    }
}

// -------------------- setup: compaction --------------------
__global__ void setup_kernel(const void* __restrict__ targets_raw)
{
    __shared__ int s0[1024];
    __shared__ int s1[1024];
    __shared__ int is64_s;
    const int t = threadIdx.x;
    if (t == 0) {
        const int* ti = (const int*)targets_raw;
        int allz = 1;
        for (int i = 1; i < 128; i += 2) if (ti[i] != 0) { allz = 0; break; }
        is64_s = allz;
    }
    __syncthreads();
    const bool is64 = (is64_s != 0);

    int cls[8]; int c0 = 0, c1 = 0;
    #pragma unroll
    for (int i = 0; i < 8; i++) {
        const int idx = t * 8 + i;
        long long v = is64 ? ((const long long*)targets_raw)[idx]
                           : (long long)((const int*)targets_raw)[idx];
        int c = 0;
        if (v >= CUT1) c = 2; else if (v >= CUT0) c = 1;
        cls[i] = c;
        if (c == 1) c0++; else if (c == 2) c1++;
    }
    s0[t] = c0; s1[t] = c1;
    __syncthreads();
    for (int off = 1; off < 1024; off <<= 1) {
        int a0 = (t >= off) ? s0[t - off] : 0;
        int a1 = (t >= off) ? s1[t - off] : 0;
        __syncthreads();
        s0[t] += a0; s1[t] += a1;
        __syncthreads();
    }
    int b0 = s0[t] - c0, b1 = s1[t] - c1;
    #pragma unroll
    for (int i = 0; i < 8; i++) {
        const int idx = t * 8 + i;
        if (cls[i] == 1)      d_idx0[b0++] = idx;
        else if (cls[i] == 2) d_idx1[b1++] = idx;
    }
    if (t == 1023) {
        d_n0 = s0[1023];
        d_n1 = s1[1023];
        d_coff1 = (long long)s0[1023] * 18000LL;
    }
}

// -------------------- conversions --------------------
__global__ void split_kernel(const float4* __restrict__ src,
                             __nv_bfloat162* __restrict__ hi,
                             __nv_bfloat162* __restrict__ lo, long long n4)
{
    long long i = blockIdx.x * (long long)blockDim.x + threadIdx.x;
    const long long stride = gridDim.x * (long long)blockDim.x;
    for (; i < n4; i += stride) {
        float4 v = src[i];
        __nv_bfloat16 h0 = __float2bfloat16(v.x);
        __nv_bfloat16 h1 = __float2bfloat16(v.y);
        __nv_bfloat16 h2 = __float2bfloat16(v.z);
        __nv_bfloat16 h3 = __float2bfloat16(v.w);
        hi[i*2+0] = __halves2bfloat162(h0, h1);
        hi[i*2+1] = __halves2bfloat162(h2, h3);
        lo[i*2+0] = __halves2bfloat162(__float2bfloat16(v.x - __bfloat162float(h0)),
                                       __float2bfloat16(v.y - __bfloat162float(h1)));
        lo[i*2+1] = __halves2bfloat162(__float2bfloat16(v.z - __bfloat162float(h2)),
                                       __float2bfloat16(v.w - __bfloat162float(h3)));
    }
}

__global__ void tofp16_kernel(const float4* __restrict__ src,
                              __half2* __restrict__ dst, long long n4)
{
    long long i = blockIdx.x * (long long)blockDim.x + threadIdx.x;
    const long long stride = gridDim.x * (long long)blockDim.x;
    for (; i < n4; i += stride) {
        float4 v = src[i];
        dst[i*2+0] = __floats2half2_rn(v.x, v.y);
        dst[i*2+1] = __floats2half2_rn(v.z, v.w);
    }
}

// head B: rows [0:2000) = embed fp32->fp16, rows [2000:2002) = tailW
__global__ void pack_head16(const float* __restrict__ embed,
                            const float* __restrict__ tailW)
{
    const int row = blockIdx.x;       // 0..2001
    const float* src = (row < CUT0) ? embed + (long long)row * HDIM
                                    : tailW + (long long)(row - CUT0) * HDIM;
    __half* dst = g_hb16 + (long long)row * HDIM;
    for (int i = threadIdx.x; i < HDIM; i += blockDim.x)
        dst[i] = __float2half_rn(src[i]);
}
__global__ void pack_head_bias(const float* __restrict__ sbias,
                               const float* __restrict__ tailb)
{
    const int i = blockIdx.x * blockDim.x + threadIdx.x;
    if (i < HEAD_NP)
        g_hbias[i] = (i < CUT0) ? sbias[i] : ((i < HEAD_N) ? tailb[i - CUT0] : 0.f);
}

// gather compacted hidden rows (bf16 hi/lo)
__global__ void gather_rows(const __nv_bfloat16* __restrict__ hhi,
                            const __nv_bfloat16* __restrict__ hlo,
                            const int* __restrict__ idx, const int* __restrict__ n,
                            __nv_bfloat16* __restrict__ ghi, __nv_bfloat16* __restrict__ glo)
{
    const int b = blockIdx.x;
    if (b >= *n) return;
    const int r = idx[b];
    const uint4* sh = (const uint4*)(hhi + (long long)r * HDIM);
    const uint4* sl = (const uint4*)(hlo + (long long)r * HDIM);
    uint4* dh = (uint4*)(ghi + (long long)b * HDIM);
    uint4* dl = (uint4*)(glo + (long long)b * HDIM);
    for (int i = threadIdx.x; i < HDIM / 8; i += blockDim.x) { dh[i] = sh[i]; dl[i] = sl[i]; }
}

// -------------------- host launch --------------------
extern "C" void kernel_launch(void* const* d_in, const int* in_sizes, int n_in,
                              void* d_out, int out_size)
{
    const float* hidden = (const float*)d_in[0];
    const float* embed  = (const float*)d_in[1];
    const float* tailW  = (const float*)d_in[2];
    const float* tailb  = (const float*)d_in[3];
    const float* sbias  = (const float*)d_in[4];
    const float* bias0  = (const float*)d_in[5];
    const float* bias1  = (const float*)d_in[6];
    const float* down0  = (const float*)d_in[7];
    const float* down1  = (const float*)d_in[8];
    const void*  targs  = d_in[9];
    float* out = (float*)d_out;

    #define SYM(p, s) void* p; cudaGetSymbolAddress(&p, s)
    SYM(p_hhi, g_h_hi);  SYM(p_hlo, g_h_lo);
    SYM(p_ehi, g_e_hi);  SYM(p_elo, g_e_lo);
    SYM(p_d0h, g_d0_hi); SYM(p_d0l, g_d0_lo);
    SYM(p_d1h, g_d1_hi); SYM(p_d1l, g_d1_lo);
    SYM(p_g0h, g_g0_hi); SYM(p_g0l, g_g0_lo);
    SYM(p_g1h, g_g1_hi); SYM(p_g1l, g_g1_lo);
    SYM(p_h16, g_h16);   SYM(p_hb16, g_hb16); SYM(p_hbias, g_hbias);
    SYM(p_dc0, g_dec0h); SYM(p_dc1, g_dec1h);
    SYM(p_p0, g_p0h);    SYM(p_p1, g_p1h);
    SYM(p_i0, d_idx0);   SYM(p_i1, d_idx1);
    SYM(p_n0, d_n0);     SYM(p_n1, d_n1);   SYM(p_c1, d_coff1);
    #undef SYM

    cudaFuncSetAttribute(gemm3, cudaFuncAttributeMaxDynamicSharedMemorySize, A_SMEM);
    cudaFuncSetAttribute(gemm1, cudaFuncAttributeMaxDynamicSharedMemorySize, B_SMEM);

    // setup + operand conversion
    setup_kernel<<<1, 1024>>>(targs);
    split_kernel<<<4096, 256>>>((const float4*)hidden, (__nv_bfloat162*)p_hhi,
                                (__nv_bfloat162*)p_hlo, (long long)BATCH * HDIM / 4);
    // embed rows [2000:50000) only (head uses fp16 pack below)
    split_kernel<<<16384, 256>>>((const float4*)(embed + (long long)CUT0 * HDIM),
                                 (__nv_bfloat162*)((__nv_bfloat16*)p_ehi + (long long)CUT0 * HDIM),
                                 (__nv_bfloat162*)((__nv_bfloat16*)p_elo + (long long)CUT0 * HDIM),
                                 48000LL * HDIM / 4);
    split_kernel<<<1024, 256>>>((const float4*)down0, (__nv_bfloat162*)p_d0h,
                                (__nv_bfloat162*)p_d0l, 1024LL * HDIM / 4);
    split_kernel<<<256, 256>>>((const float4*)down1, (__nv_bfloat162*)p_d1h,
                               (__nv_bfloat162*)p_d1l, 256LL * HDIM / 4);
    tofp16_kernel<<<4096, 256>>>((const float4*)hidden, (__half2*)p_h16,
                                 (long long)BATCH * HDIM / 4);
    pack_head16<<<HEAD_N, 256>>>(embed, tailW);
    pack_head_bias<<<8, 256>>>(sbias, tailb);
    gather_rows<<<BATCH, 128>>>((const __nv_bfloat16*)p_hhi, (const __nv_bfloat16*)p_hlo,
                                (const int*)p_i0, (const int*)p_n0,
                                (__nv_bfloat16*)p_g0h, (__nv_bfloat16*)p_g0l);
    gather_rows<<<BATCH, 128>>>((const __nv_bfloat16*)p_hhi, (const __nv_bfloat16*)p_hlo,
                                (const int*)p_i1, (const int*)p_n1,
                                (__nv_bfloat16*)p_g1h, (__nv_bfloat16*)p_g1l);

    #define BF(p) (const __nv_bfloat16*)(p)
    // ---- intermediates: bf16 3-split -> fp16 ----
    // dec0: [18000 x 1024] = embed[2000:20000] @ down0^T
    gemm3<<<dim3(8, 141), 256, A_SMEM>>>(
        BF(p_ehi) + (long long)CUT0 * HDIM, BF(p_elo) + (long long)CUT0 * HDIM,
        BF(p_d0h), BF(p_d0l),
        HDIM, 1024, DEC0_M, nullptr, (__half*)p_dc0, 1024LL);
    // p0: [n0 x 1024] = hidden[idx0] @ down0^T
    gemm3<<<dim3(8, 64), 256, A_SMEM>>>(
        BF(p_g0h), BF(p_g0l), BF(p_d0h), BF(p_d0l),
        HDIM, 1024, 0, (const int*)p_n0, (__half*)p_p0, 1024LL);
    // dec1: [30000 x 256] = embed[20000:50000] @ down1^T
    gemm3<<<dim3(2, 235), 256, A_SMEM>>>(
        BF(p_ehi) + (long long)CUT1 * HDIM, BF(p_elo) + (long long)CUT1 * HDIM,
        BF(p_d1h), BF(p_d1l),
        HDIM, 256, DEC1_M, nullptr, (__half*)p_dc1, 256LL);
    // p1: [n1 x 256] = hidden[idx1] @ down1^T
    gemm3<<<dim3(2, 64), 256, A_SMEM>>>(
        BF(p_g1h), BF(p_g1l), BF(p_d1h), BF(p_d1l),
        HDIM, 256, 0, (const int*)p_n1, (__half*)p_p1, 256LL);
    #undef BF

    // ---- outputs: single-pass fp16 ----
    // head: [8192 x 2002]
    gemm1<<<dim3(16, 64), 256, B_SMEM>>>(
        (const __half*)p_h16, (const __half*)p_hb16,
        HDIM, HEAD_N, BATCH, nullptr,
        out, (const float*)p_hbias, (long long)HEAD_N, nullptr);
    // out0: [n0 x 18000]
    gemm1<<<dim3(141, 64), 256, B_SMEM>>>(
        (const __half*)p_p0, (const __half*)p_dc0,
        HDIM, DEC0_M, 0, (const int*)p_n0,
        out + HEAD_ELEMS, bias0, 18000LL, nullptr);
    // out1: [n1 x 30000]
    gemm1<<<dim3(235, 64), 256, B_SMEM>>>(
        (const __half*)p_p1, (const __half*)p_dc1,
        256, DEC1_M, 0, (const int*)p_n1,
        out + HEAD_ELEMS, bias1, 30000LL, (const long long*)p_c1);
}

// round 5
// speedup vs baseline: 8.8908x; 1.4342x over previous
#include <cuda_runtime.h>
#include <cuda_bf16.h>
#include <cuda_fp16.h>
#include <cstdint>

// ---------------------------------------------------------------------------
// AdaptiveLogits, all GEMMs single-pass fp16 on mma.sync (fp32 accumulate).
// Error budget: each GEMM ~1.6e-4 (measured R4); 2-stage chains RSS ~2.8e-4.
// 3-stage cp.async pipeline, 128x128x32 tiles, 256 thr, 2 CTAs/SM.
// ---------------------------------------------------------------------------

#define BATCH 8192
#define HDIM  1024
#define CUT0  2000
#define CUT1  20000
#define HEAD_N 2002
#define HEAD_NP 2048
#define HEAD_ELEMS (8192LL*2002LL)
#define DEC0_M 18000
#define DEC1_M 30000
#define DEC0_ROWS 18176
#define DEC1_ROWS 30208
#define E_ROWS  50176

// -------------------- device scratch (zero-init; no allocs allowed) --------
__device__ __align__(256) __half g_h16  [BATCH*HDIM];
__device__ __align__(256) __half g_e16  [E_ROWS*HDIM];     // rows [2000,50000)
__device__ __align__(256) __half g_hb16 [HEAD_NP*HDIM];
__device__ __align__(256) float  g_hbias[HEAD_NP];
__device__ __align__(256) __half g_d016 [1024*HDIM];
__device__ __align__(256) __half g_d116 [256*HDIM];
__device__ __align__(256) __half g_g016 [BATCH*HDIM];
__device__ __align__(256) __half g_g116 [BATCH*HDIM];
__device__ __align__(256) __half g_dec0h[DEC0_ROWS*HDIM];
__device__ __align__(256) __half g_dec1h[DEC1_ROWS*256];
__device__ __align__(256) __half g_p0h  [BATCH*HDIM];
__device__ __align__(256) __half g_p1h  [BATCH*256];
__device__ int  d_idx0[BATCH];
__device__ int  d_idx1[BATCH];
__device__ int  d_n0;
__device__ int  d_n1;
__device__ long long d_coff1;

// -------------------- PTX helpers --------------------
__device__ __forceinline__ uint32_t smem_u32(const void* p) {
    return (uint32_t)__cvta_generic_to_shared(p);
}
__device__ __forceinline__ void cp16(uint32_t dst, const void* src) {
    asm volatile("cp.async.cg.shared.global [%0], [%1], 16;" :: "r"(dst), "l"(src) : "memory");
}
__device__ __forceinline__ void ldm4(uint32_t* r, uint32_t addr) {
    asm volatile("ldmatrix.sync.aligned.m8n8.x4.shared.b16 {%0,%1,%2,%3}, [%4];"
                 : "=r"(r[0]), "=r"(r[1]), "=r"(r[2]), "=r"(r[3]) : "r"(addr));
}
__device__ __forceinline__ void mma_f16(float* c, const uint32_t* a, const uint32_t* b) {
    asm volatile(
        "mma.sync.aligned.m16n8k16.row.col.f32.f16.f16.f32 "
        "{%0,%1,%2,%3}, {%4,%5,%6,%7}, {%8,%9}, {%0,%1,%2,%3};"
        : "+f"(c[0]), "+f"(c[1]), "+f"(c[2]), "+f"(c[3])
        : "r"(a[0]), "r"(a[1]), "r"(a[2]), "r"(a[3]), "r"(b[0]), "r"(b[1]));
}

// -------------------- tile geometry --------------------
#define ROWB 80                    // 32 halves padded to 80B (conflict-free)
#define MAT_BYTES (128*ROWB)       // 10240
#define ST_BYTES  (2*MAT_BYTES)    // A + B per stage = 20480
#define NSTAGE 3
#define SMEM_BYTES (NSTAGE*ST_BYTES)   // 61440

__device__ __forceinline__ void load_stage(
    uint32_t s,
    const char* Ah, long long aRB, int aRow0,
    const char* Bh, long long bRB, int bRow0,
    long long kByte, int tid)
{
    #pragma unroll
    for (int i = 0; i < 2; i++) {
        const int u = tid + i * 256;
        const int row = u >> 2;
        const int ch  = u & 3;
        const uint32_t d = (uint32_t)(row * ROWB + ch * 16);
        cp16(s + d,             Ah + (long long)(aRow0 + row) * aRB + kByte + ch * 16);
        cp16(s + MAT_BYTES + d, Bh + (long long)(bRow0 + row) * bRB + kByte + ch * 16);
    }
}

// -------------------- GEMM: C = A * B^T, fp16 in, fp32 acc -----------------
// OUTMODE 0: fp32 out (+bias, +*coff)   OUTMODE 1: fp16 out
template <int OUTMODE>
__global__ void __launch_bounds__(256, 2)
hgemm(const __half* __restrict__ Ah_, const __half* __restrict__ Bh_,
      int K, int N, int Mstatic, const int* __restrict__ Mdev,
      float* __restrict__ Cf, const float* __restrict__ bias,
      long long cld, const long long* __restrict__ coff,
      __half* __restrict__ Ch)
{
    const int M = Mdev ? *Mdev : Mstatic;
    const int mBlk = blockIdx.y * 128;
    if (mBlk >= M) return;
    const int nBlk = blockIdx.x * 128;

    extern __shared__ __align__(1024) char smem[];
    const uint32_t sb = smem_u32(smem);
    const int tid = threadIdx.x;
    const int lane = tid & 31;
    const int wid = tid >> 5;
    const int wm = (wid & 1) * 64;
    const int wn = (wid >> 1) * 32;

    const char* Ah = (const char*)Ah_;
    const char* Bh = (const char*)Bh_;
    const long long aRB = (long long)K * 2;
    const long long bRB = (long long)K * 2;
    const int nk = K >> 5;

    float acc[4][4][4];
    #pragma unroll
    for (int i = 0; i < 4; i++)
        #pragma unroll
        for (int j = 0; j < 4; j++)
            #pragma unroll
            for (int k = 0; k < 4; k++) acc[i][j][k] = 0.f;

    const uint32_t aRowOff = (uint32_t)((wm + (lane & 15)) * ROWB);
    const uint32_t aColOff = (uint32_t)((lane >> 4) * 16);
    const uint32_t bRowOff = (uint32_t)((wn + ((lane >> 4) & 1) * 8 + (lane & 7)) * ROWB);
    const uint32_t bColOff = (uint32_t)(((lane >> 3) & 1) * 16);

    // prologue: stages 0,1
    load_stage(sb, Ah, aRB, mBlk, Bh, bRB, nBlk, 0, tid);
    asm volatile("cp.async.commit_group;" ::: "memory");
    if (nk > 1) {
        load_stage(sb + ST_BYTES, Ah, aRB, mBlk, Bh, bRB, nBlk, 64, tid);
        asm volatile("cp.async.commit_group;" ::: "memory");
    }

    int stage = 0;
    for (int c = 0; c < nk; c++) {
        if (c + 1 < nk)
            asm volatile("cp.async.wait_group 1;" ::: "memory");
        else
            asm volatile("cp.async.wait_group 0;" ::: "memory");
        __syncthreads();
        if (c + 2 < nk) {
            int ns = stage + 2; if (ns >= NSTAGE) ns -= NSTAGE;
            load_stage(sb + (uint32_t)ns * ST_BYTES,
                       Ah, aRB, mBlk, Bh, bRB, nBlk,
                       (long long)(c + 2) * 64, tid);
            asm volatile("cp.async.commit_group;" ::: "memory");
        }
        const uint32_t st = sb + (uint32_t)stage * ST_BYTES;

        #pragma unroll
        for (int k16 = 0; k16 < 2; k16++) {
            uint32_t af[4][4], bf[2][4];
            const uint32_t ak = (uint32_t)(k16 * 32) + aColOff;
            const uint32_t bk = (uint32_t)(k16 * 32) + bColOff;
            #pragma unroll
            for (int mt = 0; mt < 4; mt++)
                ldm4(af[mt], st + aRowOff + (uint32_t)(mt * 16 * ROWB) + ak);
            #pragma unroll
            for (int g = 0; g < 2; g++)
                ldm4(bf[g], st + MAT_BYTES + bRowOff + (uint32_t)(g * 16 * ROWB) + bk);
            #pragma unroll
            for (int mt = 0; mt < 4; mt++)
                #pragma unroll
                for (int nt = 0; nt < 4; nt++)
                    mma_f16(acc[mt][nt], af[mt], &bf[nt >> 1][(nt & 1) * 2]);
        }
        if (++stage >= NSTAGE) stage = 0;
    }

    const long long cOff = (OUTMODE == 0 && coff) ? *coff : 0LL;
    const int r = lane >> 2;
    const int cq = (lane & 3) * 2;
    #pragma unroll
    for (int mt = 0; mt < 4; mt++) {
        #pragma unroll
        for (int nt = 0; nt < 4; nt++) {
            const int m0 = mBlk + wm + mt * 16 + r;
            const int n  = nBlk + wn + nt * 8 + cq;
            if (n >= N) continue;
            const float* a4 = acc[mt][nt];
            if (OUTMODE == 0) {
                const float b0 = bias[n], b1 = bias[n + 1];
                if (m0 < M)
                    *(float2*)(Cf + cOff + (long long)m0 * cld + n) =
                        make_float2(a4[0] + b0, a4[1] + b1);
                if (m0 + 8 < M)
                    *(float2*)(Cf + cOff + (long long)(m0 + 8) * cld + n) =
                        make_float2(a4[2] + b0, a4[3] + b1);
            } else {
                if (m0 < M)
                    *(__half2*)(Ch + (long long)m0 * cld + n) =
                        __floats2half2_rn(a4[0], a4[1]);
                if (m0 + 8 < M)
                    *(__half2*)(Ch + (long long)(m0 + 8) * cld + n) =
                        __floats2half2_rn(a4[2], a4[3]);
            }
        }
    }
}

// -------------------- setup: compaction --------------------
__global__ void setup_kernel(const void* __restrict__ targets_raw)
{
    __shared__ int s0[1024];
    __shared__ int s1[1024];
    __shared__ int is64_s;
    const int t = threadIdx.x;
    if (t == 0) {
        const int* ti = (const int*)targets_raw;
        int allz = 1;
        for (int i = 1; i < 128; i += 2) if (ti[i] != 0) { allz = 0; break; }
        is64_s = allz;
    }
    __syncthreads();
    const bool is64 = (is64_s != 0);

    int cls[8]; int c0 = 0, c1 = 0;
    #pragma unroll
    for (int i = 0; i < 8; i++) {
        const int idx = t * 8 + i;
        long long v = is64 ? ((const long long*)targets_raw)[idx]
                           : (long long)((const int*)targets_raw)[idx];
        int c = 0;
        if (v >= CUT1) c = 2; else if (v >= CUT0) c = 1;
        cls[i] = c;
        if (c == 1) c0++; else if (c == 2) c1++;
    }
    s0[t] = c0; s1[t] = c1;
    __syncthreads();
    for (int off = 1; off < 1024; off <<= 1) {
        int a0 = (t >= off) ? s0[t - off] : 0;
        int a1 = (t >= off) ? s1[t - off] : 0;
        __syncthreads();
        s0[t] += a0; s1[t] += a1;
        __syncthreads();
    }
    int b0 = s0[t] - c0, b1 = s1[t] - c1;
    #pragma unroll
    for (int i = 0; i < 8; i++) {
        const int idx = t * 8 + i;
        if (cls[i] == 1)      d_idx0[b0++] = idx;
        else if (cls[i] == 2) d_idx1[b1++] = idx;
    }
    if (t == 1023) {
        d_n0 = s0[1023];
        d_n1 = s1[1023];
        d_coff1 = (long long)s0[1023] * 18000LL;
    }
}

// -------------------- conversions --------------------
__global__ void tofp16_kernel(const float4* __restrict__ src,
                              __half2* __restrict__ dst, long long n4)
{
    long long i = blockIdx.x * (long long)blockDim.x + threadIdx.x;
    const long long stride = gridDim.x * (long long)blockDim.x;
    for (; i < n4; i += stride) {
        float4 v = src[i];
        dst[i*2+0] = __floats2half2_rn(v.x, v.y);
        dst[i*2+1] = __floats2half2_rn(v.z, v.w);
    }
}

// head B: rows [0:2000) = embed, rows [2000:2002) = tailW
__global__ void pack_head16(const float* __restrict__ embed,
                            const float* __restrict__ tailW)
{
    const int row = blockIdx.x;
    const float* src = (row < CUT0) ? embed + (long long)row * HDIM
                                    : tailW + (long long)(row - CUT0) * HDIM;
    __half* dst = g_hb16 + (long long)row * HDIM;
    for (int i = threadIdx.x; i < HDIM; i += blockDim.x)
        dst[i] = __float2half_rn(src[i]);
}
__global__ void pack_head_bias(const float* __restrict__ sbias,
                               const float* __restrict__ tailb)
{
    const int i = blockIdx.x * blockDim.x + threadIdx.x;
    if (i < HEAD_NP)
        g_hbias[i] = (i < CUT0) ? sbias[i] : ((i < HEAD_N) ? tailb[i - CUT0] : 0.f);
}

// gather compacted hidden rows (fp16)
__global__ void gather16(const __half* __restrict__ h16,
                         const int* __restrict__ idx, const int* __restrict__ n,
                         __half* __restrict__ g)
{
    const int b = blockIdx.x;
    if (b >= *n) return;
    const int r = idx[b];
    const uint4* s = (const uint4*)(h16 + (long long)r * HDIM);
    uint4* d = (uint4*)(g + (long long)b * HDIM);
    for (int i = threadIdx.x; i < HDIM / 8; i += blockDim.x) d[i] = s[i];
}

// -------------------- host launch --------------------
extern "C" void kernel_launch(void* const* d_in, const int* in_sizes, int n_in,
                              void* d_out, int out_size)
{
    const float* hidden = (const float*)d_in[0];
    const float* embed  = (const float*)d_in[1];
    const float* tailW  = (const float*)d_in[2];
    const float* tailb  = (const float*)d_in[3];
    const float* sbias  = (const float*)d_in[4];
    const float* bias0  = (const float*)d_in[5];
    const float* bias1  = (const float*)d_in[6];
    const float* down0  = (const float*)d_in[7];
    const float* down1  = (const float*)d_in[8];
    const void*  targs  = d_in[9];
    float* out = (float*)d_out;

    #define SYM(p, s) void* p; cudaGetSymbolAddress(&p, s)
    SYM(p_h16, g_h16);   SYM(p_e16, g_e16);
    SYM(p_hb16, g_hb16); SYM(p_hbias, g_hbias);
    SYM(p_d016, g_d016); SYM(p_d116, g_d116);
    SYM(p_g016, g_g016); SYM(p_g116, g_g116);
    SYM(p_dc0, g_dec0h); SYM(p_dc1, g_dec1h);
    SYM(p_p0, g_p0h);    SYM(p_p1, g_p1h);
    SYM(p_i0, d_idx0);   SYM(p_i1, d_idx1);
    SYM(p_n0, d_n0);     SYM(p_n1, d_n1);   SYM(p_c1, d_coff1);
    #undef SYM

    cudaFuncSetAttribute(hgemm<0>, cudaFuncAttributeMaxDynamicSharedMemorySize, SMEM_BYTES);
    cudaFuncSetAttribute(hgemm<1>, cudaFuncAttributeMaxDynamicSharedMemorySize, SMEM_BYTES);

    // setup + conversions
    setup_kernel<<<1, 1024>>>(targs);
    tofp16_kernel<<<4096, 256>>>((const float4*)hidden, (__half2*)p_h16,
                                 (long long)BATCH * HDIM / 4);
    tofp16_kernel<<<16384, 256>>>((const float4*)(embed + (long long)CUT0 * HDIM),
                                  (__half2*)((__half*)p_e16 + (long long)CUT0 * HDIM),
                                  48000LL * HDIM / 4);
    tofp16_kernel<<<1024, 256>>>((const float4*)down0, (__half2*)p_d016,
                                 1024LL * HDIM / 4);
    tofp16_kernel<<<256, 256>>>((const float4*)down1, (__half2*)p_d116,
                                256LL * HDIM / 4);
    pack_head16<<<HEAD_N, 256>>>(embed, tailW);
    pack_head_bias<<<8, 256>>>(sbias, tailb);
    gather16<<<BATCH, 128>>>((const __half*)p_h16, (const int*)p_i0,
                             (const int*)p_n0, (__half*)p_g016);
    gather16<<<BATCH, 128>>>((const __half*)p_h16, (const int*)p_i1,
                             (const int*)p_n1, (__half*)p_g116);

    #define H(p) (const __half*)(p)
    // head: [8192 x 2002] = hidden @ hb^T + hbias
    hgemm<0><<<dim3(16, 64), 256, SMEM_BYTES>>>(
        H(p_h16), H(p_hb16), HDIM, HEAD_N, BATCH, nullptr,
        out, (const float*)p_hbias, (long long)HEAD_N, nullptr, nullptr);

    // dec0: [18000 x 1024] = embed[2000:20000] @ down0^T -> fp16
    hgemm<1><<<dim3(8, 141), 256, SMEM_BYTES>>>(
        H(p_e16) + (long long)CUT0 * HDIM, H(p_d016),
        HDIM, 1024, DEC0_M, nullptr,
        nullptr, nullptr, 1024LL, nullptr, (__half*)p_dc0);

    // p0: [n0 x 1024] = hidden[idx0] @ down0^T -> fp16
    hgemm<1><<<dim3(8, 64), 256, SMEM_BYTES>>>(
        H(p_g016), H(p_d016), HDIM, 1024, 0, (const int*)p_n0,
        nullptr, nullptr, 1024LL, nullptr, (__half*)p_p0);

    // dec1: [30000 x 256] = embed[20000:50000] @ down1^T -> fp16
    hgemm<1><<<dim3(2, 235), 256, SMEM_BYTES>>>(
        H(p_e16) + (long long)CUT1 * HDIM, H(p_d116),
        HDIM, 256, DEC1_M, nullptr,
        nullptr, nullptr, 256LL, nullptr, (__half*)p_dc1);

    // p1: [n1 x 256] = hidden[idx1] @ down1^T -> fp16
    hgemm<1><<<dim3(2, 64), 256, SMEM_BYTES>>>(
        H(p_g116), H(p_d116), HDIM, 256, 0, (const int*)p_n1,
        nullptr, nullptr, 256LL, nullptr, (__half*)p_p1);

    // out0: [n0 x 18000] = p0 @ dec0^T + bias0
    hgemm<0><<<dim3(141, 64), 256, SMEM_BYTES>>>(
        H(p_p0), H(p_dc0), HDIM, DEC0_M, 0, (const int*)p_n0,
        out + HEAD_ELEMS, bias0, 18000LL, nullptr, nullptr);

    // out1: [n1 x 30000] = p1 @ dec1^T + bias1
    hgemm<0><<<dim3(235, 64), 256, SMEM_BYTES>>>(
        H(p_p1), H(p_dc1), 256, DEC1_M, 0, (const int*)p_n1,
        out + HEAD_ELEMS, bias1, 30000LL, (const long long*)p_c1, nullptr);
    #undef H
}

// round 6
// speedup vs baseline: 9.1151x; 1.0252x over previous
#include <cuda_runtime.h>
#include <cuda_bf16.h>
#include <cuda_fp16.h>
#include <cstdint>

// ---------------------------------------------------------------------------
// AdaptiveLogits, all GEMMs single-pass fp16 on mma.sync (fp32 accumulate).
// 128x128x32 CTA tile, 4 warps @ 64x64 warp tile, 4-stage cp.async pipeline.
// ---------------------------------------------------------------------------

#define BATCH 8192
#define HDIM  1024
#define CUT0  2000
#define CUT1  20000
#define HEAD_N 2002
#define HEAD_NP 2048
#define HEAD_ELEMS (8192LL*2002LL)
#define DEC0_M 18000
#define DEC1_M 30000
#define DEC0_ROWS 18176
#define DEC1_ROWS 30208
#define E_ROWS  50176

// -------------------- device scratch (zero-init; no allocs allowed) --------
__device__ __align__(256) __half g_h16  [BATCH*HDIM];
__device__ __align__(256) __half g_e16  [E_ROWS*HDIM];     // rows [2000,50000)
__device__ __align__(256) __half g_hb16 [HEAD_NP*HDIM];
__device__ __align__(256) float  g_hbias[HEAD_NP];
__device__ __align__(256) __half g_d016 [1024*HDIM];
__device__ __align__(256) __half g_d116 [256*HDIM];
__device__ __align__(256) __half g_g016 [BATCH*HDIM];
__device__ __align__(256) __half g_g116 [BATCH*HDIM];
__device__ __align__(256) __half g_dec0h[DEC0_ROWS*HDIM];
__device__ __align__(256) __half g_dec1h[DEC1_ROWS*256];
__device__ __align__(256) __half g_p0h  [BATCH*HDIM];
__device__ __align__(256) __half g_p1h  [BATCH*256];
__device__ int  d_idx0[BATCH];
__device__ int  d_idx1[BATCH];
__device__ int  d_n0;
__device__ int  d_n1;
__device__ long long d_coff1;

// -------------------- PTX helpers --------------------
__device__ __forceinline__ uint32_t smem_u32(const void* p) {
    return (uint32_t)__cvta_generic_to_shared(p);
}
__device__ __forceinline__ void cp16(uint32_t dst, const void* src) {
    asm volatile("cp.async.cg.shared.global [%0], [%1], 16;" :: "r"(dst), "l"(src) : "memory");
}
__device__ __forceinline__ void ldm4(uint32_t* r, uint32_t addr) {
    asm volatile("ldmatrix.sync.aligned.m8n8.x4.shared.b16 {%0,%1,%2,%3}, [%4];"
                 : "=r"(r[0]), "=r"(r[1]), "=r"(r[2]), "=r"(r[3]) : "r"(addr));
}
__device__ __forceinline__ void mma_f16(float* c, const uint32_t* a, const uint32_t* b) {
    asm volatile(
        "mma.sync.aligned.m16n8k16.row.col.f32.f16.f16.f32 "
        "{%0,%1,%2,%3}, {%4,%5,%6,%7}, {%8,%9}, {%0,%1,%2,%3};"
        : "+f"(c[0]), "+f"(c[1]), "+f"(c[2]), "+f"(c[3])
        : "r"(a[0]), "r"(a[1]), "r"(a[2]), "r"(a[3]), "r"(b[0]), "r"(b[1]));
}

// -------------------- tile geometry --------------------
#define ROWB 80                    // 32 halves padded to 80B (conflict-free)
#define MAT_BYTES (128*ROWB)       // 10240
#define ST_BYTES  (2*MAT_BYTES)    // A + B per stage = 20480
#define NSTAGE 4
#define SMEM_BYTES (NSTAGE*ST_BYTES)   // 81920

// 128 threads: 1024 cp16 per stage -> 8 per thread
__device__ __forceinline__ void load_stage(
    uint32_t s,
    const char* Ah, long long aRB, int aRow0,
    const char* Bh, long long bRB, int bRow0,
    long long kByte, int tid)
{
    #pragma unroll
    for (int i = 0; i < 4; i++) {
        const int u = tid + i * 128;        // 0..511
        const int row = u >> 2;
        const int ch  = u & 3;
        const uint32_t d = (uint32_t)(row * ROWB + ch * 16);
        cp16(s + d,             Ah + (long long)(aRow0 + row) * aRB + kByte + ch * 16);
        cp16(s + MAT_BYTES + d, Bh + (long long)(bRow0 + row) * bRB + kByte + ch * 16);
    }
}

// -------------------- GEMM: C = A * B^T, fp16 in, fp32 acc -----------------
// OUTMODE 0: fp32 out (+bias, +*coff)   OUTMODE 1: fp16 out
template <int OUTMODE>
__global__ void __launch_bounds__(128, 2)
hgemm(const __half* __restrict__ Ah_, const __half* __restrict__ Bh_,
      int K, int N, int Mstatic, const int* __restrict__ Mdev,
      float* __restrict__ Cf, const float* __restrict__ bias,
      long long cld, const long long* __restrict__ coff,
      __half* __restrict__ Ch)
{
    const int M = Mdev ? *Mdev : Mstatic;
    const int mBlk = blockIdx.y * 128;
    if (mBlk >= M) return;
    const int nBlk = blockIdx.x * 128;

    extern __shared__ __align__(1024) char smem[];
    const uint32_t sb = smem_u32(smem);
    const int tid = threadIdx.x;
    const int lane = tid & 31;
    const int wid = tid >> 5;            // 0..3
    const int wm = (wid & 1) * 64;
    const int wn = (wid >> 1) * 64;

    const char* Ah = (const char*)Ah_;
    const char* Bh = (const char*)Bh_;
    const long long aRB = (long long)K * 2;
    const long long bRB = (long long)K * 2;
    const int nk = K >> 5;

    float acc[4][8][4];
    #pragma unroll
    for (int i = 0; i < 4; i++)
        #pragma unroll
        for (int j = 0; j < 8; j++)
            #pragma unroll
            for (int k = 0; k < 4; k++) acc[i][j][k] = 0.f;

    const uint32_t aRowOff = (uint32_t)((wm + (lane & 15)) * ROWB);
    const uint32_t aColOff = (uint32_t)((lane >> 4) * 16);
    const uint32_t bRowOff = (uint32_t)((wn + ((lane >> 4) & 1) * 8 + (lane & 7)) * ROWB);
    const uint32_t bColOff = (uint32_t)(((lane >> 3) & 1) * 16);

    // prologue: stages 0..2
    load_stage(sb, Ah, aRB, mBlk, Bh, bRB, nBlk, 0, tid);
    asm volatile("cp.async.commit_group;" ::: "memory");
    if (nk > 1) {
        load_stage(sb + ST_BYTES, Ah, aRB, mBlk, Bh, bRB, nBlk, 64, tid);
        asm volatile("cp.async.commit_group;" ::: "memory");
    }
    if (nk > 2) {
        load_stage(sb + 2 * ST_BYTES, Ah, aRB, mBlk, Bh, bRB, nBlk, 128, tid);
        asm volatile("cp.async.commit_group;" ::: "memory");
    }

    int stage = 0;
    for (int c = 0; c < nk; c++) {
        const int rem = nk - 1 - c;          // stages still loading after this one
        if (rem >= 2)
            asm volatile("cp.async.wait_group 2;" ::: "memory");
        else if (rem == 1)
            asm volatile("cp.async.wait_group 1;" ::: "memory");
        else
            asm volatile("cp.async.wait_group 0;" ::: "memory");
        __syncthreads();
        if (c + 3 < nk) {
            int ns = stage + 3; if (ns >= NSTAGE) ns -= NSTAGE;
            load_stage(sb + (uint32_t)ns * ST_BYTES,
                       Ah, aRB, mBlk, Bh, bRB, nBlk,
                       (long long)(c + 3) * 64, tid);
            asm volatile("cp.async.commit_group;" ::: "memory");
        }
        const uint32_t st = sb + (uint32_t)stage * ST_BYTES;

        #pragma unroll
        for (int k16 = 0; k16 < 2; k16++) {
            uint32_t af[4][4], bf[4][4];
            const uint32_t ak = (uint32_t)(k16 * 32) + aColOff;
            const uint32_t bk = (uint32_t)(k16 * 32) + bColOff;
            #pragma unroll
            for (int mt = 0; mt < 4; mt++)
                ldm4(af[mt], st + aRowOff + (uint32_t)(mt * 16 * ROWB) + ak);
            #pragma unroll
            for (int g = 0; g < 4; g++)
                ldm4(bf[g], st + MAT_BYTES + bRowOff + (uint32_t)(g * 16 * ROWB) + bk);
            #pragma unroll
            for (int mt = 0; mt < 4; mt++)
                #pragma unroll
                for (int nt = 0; nt < 8; nt++)
                    mma_f16(acc[mt][nt], af[mt], &bf[nt >> 1][(nt & 1) * 2]);
        }
        if (++stage >= NSTAGE) stage = 0;
    }

    const long long cOff = (OUTMODE == 0 && coff) ? *coff : 0LL;
    const int r = lane >> 2;
    const int cq = (lane & 3) * 2;
    #pragma unroll
    for (int mt = 0; mt < 4; mt++) {
        #pragma unroll
        for (int nt = 0; nt < 8; nt++) {
            const int m0 = mBlk + wm + mt * 16 + r;
            const int n  = nBlk + wn + nt * 8 + cq;
            if (n >= N) continue;
            const float* a4 = acc[mt][nt];
            if (OUTMODE == 0) {
                const float b0 = bias[n], b1 = bias[n + 1];
                if (m0 < M)
                    *(float2*)(Cf + cOff + (long long)m0 * cld + n) =
                        make_float2(a4[0] + b0, a4[1] + b1);
                if (m0 + 8 < M)
                    *(float2*)(Cf + cOff + (long long)(m0 + 8) * cld + n) =
                        make_float2(a4[2] + b0, a4[3] + b1);
            } else {
                if (m0 < M)
                    *(__half2*)(Ch + (long long)m0 * cld + n) =
                        __floats2half2_rn(a4[0], a4[1]);
                if (m0 + 8 < M)
                    *(__half2*)(Ch + (long long)(m0 + 8) * cld + n) =
                        __floats2half2_rn(a4[2], a4[3]);
            }
        }
    }
}

// -------------------- setup: compaction --------------------
__global__ void setup_kernel(const void* __restrict__ targets_raw)
{
    __shared__ int s0[1024];
    __shared__ int s1[1024];
    __shared__ int is64_s;
    const int t = threadIdx.x;
    if (t == 0) {
        const int* ti = (const int*)targets_raw;
        int allz = 1;
        for (int i = 1; i < 128; i += 2) if (ti[i] != 0) { allz = 0; break; }
        is64_s = allz;
    }
    __syncthreads();
    const bool is64 = (is64_s != 0);

    int cls[8]; int c0 = 0, c1 = 0;
    #pragma unroll
    for (int i = 0; i < 8; i++) {
        const int idx = t * 8 + i;
        long long v = is64 ? ((const long long*)targets_raw)[idx]
                           : (long long)((const int*)targets_raw)[idx];
        int c = 0;
        if (v >= CUT1) c = 2; else if (v >= CUT0) c = 1;
        cls[i] = c;
        if (c == 1) c0++; else if (c == 2) c1++;
    }
    s0[t] = c0; s1[t] = c1;
    __syncthreads();
    for (int off = 1; off < 1024; off <<= 1) {
        int a0 = (t >= off) ? s0[t - off] : 0;
        int a1 = (t >= off) ? s1[t - off] : 0;
        __syncthreads();
        s0[t] += a0; s1[t] += a1;
        __syncthreads();
    }
    int b0 = s0[t] - c0, b1 = s1[t] - c1;
    #pragma unroll
    for (int i = 0; i < 8; i++) {
        const int idx = t * 8 + i;
        if (cls[i] == 1)      d_idx0[b0++] = idx;
        else if (cls[i] == 2) d_idx1[b1++] = idx;
    }
    if (t == 1023) {
        d_n0 = s0[1023];
        d_n1 = s1[1023];
        d_coff1 = (long long)s0[1023] * 18000LL;
    }
}

// -------------------- conversions --------------------
__global__ void tofp16_kernel(const float4* __restrict__ src,
                              __half2* __restrict__ dst, long long n4)
{
    long long i = blockIdx.x * (long long)blockDim.x + threadIdx.x;
    const long long stride = gridDim.x * (long long)blockDim.x;
    for (; i < n4; i += stride) {
        float4 v = src[i];
        dst[i*2+0] = __floats2half2_rn(v.x, v.y);
        dst[i*2+1] = __floats2half2_rn(v.z, v.w);
    }
}

// head B: rows [0:2000) = embed, rows [2000:2002) = tailW
__global__ void pack_head16(const float* __restrict__ embed,
                            const float* __restrict__ tailW)
{
    const int row = blockIdx.x;
    const float* src = (row < CUT0) ? embed + (long long)row * HDIM
                                    : tailW + (long long)(row - CUT0) * HDIM;
    __half* dst = g_hb16 + (long long)row * HDIM;
    for (int i = threadIdx.x; i < HDIM; i += blockDim.x)
        dst[i] = __float2half_rn(src[i]);
}
__global__ void pack_head_bias(const float* __restrict__ sbias,
                               const float* __restrict__ tailb)
{
    const int i = blockIdx.x * blockDim.x + threadIdx.x;
    if (i < HEAD_NP)
        g_hbias[i] = (i < CUT0) ? sbias[i] : ((i < HEAD_N) ? tailb[i - CUT0] : 0.f);
}

// gather compacted hidden rows (fp16)
__global__ void gather16(const __half* __restrict__ h16,
                         const int* __restrict__ idx, const int* __restrict__ n,
                         __half* __restrict__ g)
{
    const int b = blockIdx.x;
    if (b >= *n) return;
    const int r = idx[b];
    const uint4* s = (const uint4*)(h16 + (long long)r * HDIM);
    uint4* d = (uint4*)(g + (long long)b * HDIM);
    for (int i = threadIdx.x; i < HDIM / 8; i += blockDim.x) d[i] = s[i];
}

// -------------------- host launch --------------------
extern "C" void kernel_launch(void* const* d_in, const int* in_sizes, int n_in,
                              void* d_out, int out_size)
{
    const float* hidden = (const float*)d_in[0];
    const float* embed  = (const float*)d_in[1];
    const float* tailW  = (const float*)d_in[2];
    const float* tailb  = (const float*)d_in[3];
    const float* sbias  = (const float*)d_in[4];
    const float* bias0  = (const float*)d_in[5];
    const float* bias1  = (const float*)d_in[6];
    const float* down0  = (const float*)d_in[7];
    const float* down1  = (const float*)d_in[8];
    const void*  targs  = d_in[9];
    float* out = (float*)d_out;

    #define SYM(p, s) void* p; cudaGetSymbolAddress(&p, s)
    SYM(p_h16, g_h16);   SYM(p_e16, g_e16);
    SYM(p_hb16, g_hb16); SYM(p_hbias, g_hbias);
    SYM(p_d016, g_d016); SYM(p_d116, g_d116);
    SYM(p_g016, g_g016); SYM(p_g116, g_g116);
    SYM(p_dc0, g_dec0h); SYM(p_dc1, g_dec1h);
    SYM(p_p0, g_p0h);    SYM(p_p1, g_p1h);
    SYM(p_i0, d_idx0);   SYM(p_i1, d_idx1);
    SYM(p_n0, d_n0);     SYM(p_n1, d_n1);   SYM(p_c1, d_coff1);
    #undef SYM

    cudaFuncSetAttribute(hgemm<0>, cudaFuncAttributeMaxDynamicSharedMemorySize, SMEM_BYTES);
    cudaFuncSetAttribute(hgemm<1>, cudaFuncAttributeMaxDynamicSharedMemorySize, SMEM_BYTES);

    // setup + conversions
    setup_kernel<<<1, 1024>>>(targs);
    tofp16_kernel<<<4096, 256>>>((const float4*)hidden, (__half2*)p_h16,
                                 (long long)BATCH * HDIM / 4);
    tofp16_kernel<<<16384, 256>>>((const float4*)(embed + (long long)CUT0 * HDIM),
                                  (__half2*)((__half*)p_e16 + (long long)CUT0 * HDIM),
                                  48000LL * HDIM / 4);
    tofp16_kernel<<<1024, 256>>>((const float4*)down0, (__half2*)p_d016,
                                 1024LL * HDIM / 4);
    tofp16_kernel<<<256, 256>>>((const float4*)down1, (__half2*)p_d116,
                                256LL * HDIM / 4);
    pack_head16<<<HEAD_N, 256>>>(embed, tailW);
    pack_head_bias<<<8, 256>>>(sbias, tailb);
    gather16<<<BATCH, 128>>>((const __half*)p_h16, (const int*)p_i0,
                             (const int*)p_n0, (__half*)p_g016);
    gather16<<<BATCH, 128>>>((const __half*)p_h16, (const int*)p_i1,
                             (const int*)p_n1, (__half*)p_g116);

    #define H(p) (const __half*)(p)
    // head: [8192 x 2002] = hidden @ hb^T + hbias
    hgemm<0><<<dim3(16, 64), 128, SMEM_BYTES>>>(
        H(p_h16), H(p_hb16), HDIM, HEAD_N, BATCH, nullptr,
        out, (const float*)p_hbias, (long long)HEAD_N, nullptr, nullptr);

    // dec0: [18000 x 1024] = embed[2000:20000] @ down0^T -> fp16
    hgemm<1><<<dim3(8, 141), 128, SMEM_BYTES>>>(
        H(p_e16) + (long long)CUT0 * HDIM, H(p_d016),
        HDIM, 1024, DEC0_M, nullptr,
        nullptr, nullptr, 1024LL, nullptr, (__half*)p_dc0);

    // p0: [n0 x 1024] = hidden[idx0] @ down0^T -> fp16
    hgemm<1><<<dim3(8, 64), 128, SMEM_BYTES>>>(
        H(p_g016), H(p_d016), HDIM, 1024, 0, (const int*)p_n0,
        nullptr, nullptr, 1024LL, nullptr, (__half*)p_p0);

    // dec1: [30000 x 256] = embed[20000:50000] @ down1^T -> fp16
    hgemm<1><<<dim3(2, 235), 128, SMEM_BYTES>>>(
        H(p_e16) + (long long)CUT1 * HDIM, H(p_d116),
        HDIM, 256, DEC1_M, nullptr,
        nullptr, nullptr, 256LL, nullptr, (__half*)p_dc1);

    // p1: [n1 x 256] = hidden[idx1] @ down1^T -> fp16
    hgemm<1><<<dim3(2, 64), 128, SMEM_BYTES>>>(
        H(p_g116), H(p_d116), HDIM, 256, 0, (const int*)p_n1,
        nullptr, nullptr, 256LL, nullptr, (__half*)p_p1);

    // out0: [n0 x 18000] = p0 @ dec0^T + bias0
    hgemm<0><<<dim3(141, 64), 128, SMEM_BYTES>>>(
        H(p_p0), H(p_dc0), HDIM, DEC0_M, 0, (const int*)p_n0,
        out + HEAD_ELEMS, bias0, 18000LL, nullptr, nullptr);

    // out1: [n1 x 30000] = p1 @ dec1^T + bias1
    hgemm<0><<<dim3(235, 64), 128, SMEM_BYTES>>>(
        H(p_p1), H(p_dc1), 256, DEC1_M, 0, (const int*)p_n1,
        out + HEAD_ELEMS, bias1, 30000LL, (const long long*)p_c1, nullptr);
    #undef H
}

// round 7
// speedup vs baseline: 9.8875x; 1.0847x over previous
#include <cuda_runtime.h>
#include <cuda_bf16.h>
#include <cuda_fp16.h>
#include <cstdint>

// ---------------------------------------------------------------------------
// AdaptiveLogits, all GEMMs single-pass fp16 mma.sync (fp32 acc).
// Cluster-0 restructured: out0 = hidden0 @ (down0^T down0) @ embed0^T
//   (saves the 18.9-GMAC dec0 GEMM; T0 Gram matrix costs 1.07 GMAC)
// 128x128x32 CTA tile, 4 warps @ 64x64, 4-stage cp.async pipeline.
// ---------------------------------------------------------------------------

#define BATCH 8192
#define HDIM  1024
#define CUT0  2000
#define CUT1  20000
#define HEAD_N 2002
#define HEAD_NP 2048
#define HEAD_ELEMS (8192LL*2002LL)
#define DEC0_M 18000
#define DEC1_M 30000
#define DEC1_ROWS 30208
#define E_ROWS  50176

// -------------------- device scratch (zero-init; no allocs allowed) --------
__device__ __align__(256) __half g_h16  [BATCH*HDIM];
__device__ __align__(256) __half g_e16  [E_ROWS*HDIM];     // embed rows [2000,50176)
__device__ __align__(256) __half g_hb16 [HEAD_NP*HDIM];
__device__ __align__(256) float  g_hbias[HEAD_NP];
__device__ __align__(256) __half g_d0T  [HDIM*HDIM];       // down0^T fp16
__device__ __align__(256) __half g_T0   [HDIM*HDIM];       // down0^T @ down0
__device__ __align__(256) __half g_d116 [256*HDIM];
__device__ __align__(256) __half g_g016 [BATCH*HDIM];
__device__ __align__(256) __half g_g116 [BATCH*HDIM];
__device__ __align__(256) __half g_dec1h[DEC1_ROWS*256];
__device__ __align__(256) __half g_p0h  [BATCH*HDIM];
__device__ __align__(256) __half g_p1h  [BATCH*256];
__device__ int  d_idx0[BATCH];
__device__ int  d_idx1[BATCH];
__device__ int  d_n0;
__device__ int  d_n1;
__device__ long long d_coff1;

// -------------------- PTX helpers --------------------
__device__ __forceinline__ uint32_t smem_u32(const void* p) {
    return (uint32_t)__cvta_generic_to_shared(p);
}
__device__ __forceinline__ void cp16(uint32_t dst, const void* src) {
    asm volatile("cp.async.cg.shared.global [%0], [%1], 16;" :: "r"(dst), "l"(src) : "memory");
}
__device__ __forceinline__ void ldm4(uint32_t* r, uint32_t addr) {
    asm volatile("ldmatrix.sync.aligned.m8n8.x4.shared.b16 {%0,%1,%2,%3}, [%4];"
                 : "=r"(r[0]), "=r"(r[1]), "=r"(r[2]), "=r"(r[3]) : "r"(addr));
}
__device__ __forceinline__ void mma_f16(float* c, const uint32_t* a, const uint32_t* b) {
    asm volatile(
        "mma.sync.aligned.m16n8k16.row.col.f32.f16.f16.f32 "
        "{%0,%1,%2,%3}, {%4,%5,%6,%7}, {%8,%9}, {%0,%1,%2,%3};"
        : "+f"(c[0]), "+f"(c[1]), "+f"(c[2]), "+f"(c[3])
        : "r"(a[0]), "r"(a[1]), "r"(a[2]), "r"(a[3]), "r"(b[0]), "r"(b[1]));
}

// -------------------- tile geometry --------------------
#define ROWB 80
#define MAT_BYTES (128*ROWB)
#define ST_BYTES  (2*MAT_BYTES)
#define NSTAGE 4
#define SMEM_BYTES (NSTAGE*ST_BYTES)   // 81920

__device__ __forceinline__ void load_stage(
    uint32_t s,
    const char* Ah, long long aRB, int aRow0,
    const char* Bh, long long bRB, int bRow0,
    long long kByte, int tid)
{
    #pragma unroll
    for (int i = 0; i < 4; i++) {
        const int u = tid + i * 128;
        const int row = u >> 2;
        const int ch  = u & 3;
        const uint32_t d = (uint32_t)(row * ROWB + ch * 16);
        cp16(s + d,             Ah + (long long)(aRow0 + row) * aRB + kByte + ch * 16);
        cp16(s + MAT_BYTES + d, Bh + (long long)(bRow0 + row) * bRB + kByte + ch * 16);
    }
}

// -------------------- GEMM: C = A * B^T, fp16 in, fp32 acc -----------------
// OUTMODE 0: fp32 out (+bias, +*coff)   OUTMODE 1: fp16 out
template <int OUTMODE>
__global__ void __launch_bounds__(128, 2)
hgemm(const __half* __restrict__ Ah_, const __half* __restrict__ Bh_,
      int K, int N, int Mstatic, const int* __restrict__ Mdev,
      float* __restrict__ Cf, const float* __restrict__ bias,
      long long cld, const long long* __restrict__ coff,
      __half* __restrict__ Ch)
{
    const int M = Mdev ? *Mdev : Mstatic;
    const int mBlk = blockIdx.y * 128;
    if (mBlk >= M) return;
    const int nBlk = blockIdx.x * 128;

    extern __shared__ __align__(1024) char smem[];
    const uint32_t sb = smem_u32(smem);
    const int tid = threadIdx.x;
    const int lane = tid & 31;
    const int wid = tid >> 5;
    const int wm = (wid & 1) * 64;
    const int wn = (wid >> 1) * 64;

    const char* Ah = (const char*)Ah_;
    const char* Bh = (const char*)Bh_;
    const long long aRB = (long long)K * 2;
    const long long bRB = (long long)K * 2;
    const int nk = K >> 5;

    float acc[4][8][4];
    #pragma unroll
    for (int i = 0; i < 4; i++)
        #pragma unroll
        for (int j = 0; j < 8; j++)
            #pragma unroll
            for (int k = 0; k < 4; k++) acc[i][j][k] = 0.f;

    const uint32_t aRowOff = (uint32_t)((wm + (lane & 15)) * ROWB);
    const uint32_t aColOff = (uint32_t)((lane >> 4) * 16);
    const uint32_t bRowOff = (uint32_t)((wn + ((lane >> 4) & 1) * 8 + (lane & 7)) * ROWB);
    const uint32_t bColOff = (uint32_t)(((lane >> 3) & 1) * 16);

    load_stage(sb, Ah, aRB, mBlk, Bh, bRB, nBlk, 0, tid);
    asm volatile("cp.async.commit_group;" ::: "memory");
    if (nk > 1) {
        load_stage(sb + ST_BYTES, Ah, aRB, mBlk, Bh, bRB, nBlk, 64, tid);
        asm volatile("cp.async.commit_group;" ::: "memory");
    }
    if (nk > 2) {
        load_stage(sb + 2 * ST_BYTES, Ah, aRB, mBlk, Bh, bRB, nBlk, 128, tid);
        asm volatile("cp.async.commit_group;" ::: "memory");
    }

    int stage = 0;
    for (int c = 0; c < nk; c++) {
        const int rem = nk - 1 - c;
        if (rem >= 2)
            asm volatile("cp.async.wait_group 2;" ::: "memory");
        else if (rem == 1)
            asm volatile("cp.async.wait_group 1;" ::: "memory");
        else
            asm volatile("cp.async.wait_group 0;" ::: "memory");
        __syncthreads();
        if (c + 3 < nk) {
            int ns = stage + 3; if (ns >= NSTAGE) ns -= NSTAGE;
            load_stage(sb + (uint32_t)ns * ST_BYTES,
                       Ah, aRB, mBlk, Bh, bRB, nBlk,
                       (long long)(c + 3) * 64, tid);
            asm volatile("cp.async.commit_group;" ::: "memory");
        }
        const uint32_t st = sb + (uint32_t)stage * ST_BYTES;

        #pragma unroll
        for (int k16 = 0; k16 < 2; k16++) {
            uint32_t af[4][4], bf[4][4];
            const uint32_t ak = (uint32_t)(k16 * 32) + aColOff;
            const uint32_t bk = (uint32_t)(k16 * 32) + bColOff;
            #pragma unroll
            for (int mt = 0; mt < 4; mt++)
                ldm4(af[mt], st + aRowOff + (uint32_t)(mt * 16 * ROWB) + ak);
            #pragma unroll
            for (int g = 0; g < 4; g++)
                ldm4(bf[g], st + MAT_BYTES + bRowOff + (uint32_t)(g * 16 * ROWB) + bk);
            #pragma unroll
            for (int mt = 0; mt < 4; mt++)
                #pragma unroll
                for (int nt = 0; nt < 8; nt++)
                    mma_f16(acc[mt][nt], af[mt], &bf[nt >> 1][(nt & 1) * 2]);
        }
        if (++stage >= NSTAGE) stage = 0;
    }

    const long long cOff = (OUTMODE == 0 && coff) ? *coff : 0LL;
    const int r = lane >> 2;
    const int cq = (lane & 3) * 2;
    #pragma unroll
    for (int mt = 0; mt < 4; mt++) {
        #pragma unroll
        for (int nt = 0; nt < 8; nt++) {
            const int m0 = mBlk + wm + mt * 16 + r;
            const int n  = nBlk + wn + nt * 8 + cq;
            if (n >= N) continue;
            const float* a4 = acc[mt][nt];
            if (OUTMODE == 0) {
                const float b0 = bias[n], b1 = bias[n + 1];
                if (m0 < M)
                    *(float2*)(Cf + cOff + (long long)m0 * cld + n) =
                        make_float2(a4[0] + b0, a4[1] + b1);
                if (m0 + 8 < M)
                    *(float2*)(Cf + cOff + (long long)(m0 + 8) * cld + n) =
                        make_float2(a4[2] + b0, a4[3] + b1);
            } else {
                if (m0 < M)
                    *(__half2*)(Ch + (long long)m0 * cld + n) =
                        __floats2half2_rn(a4[0], a4[1]);
                if (m0 + 8 < M)
                    *(__half2*)(Ch + (long long)(m0 + 8) * cld + n) =
                        __floats2half2_rn(a4[2], a4[3]);
            }
        }
    }
}

// -------------------- setup: compaction --------------------
__global__ void setup_kernel(const void* __restrict__ targets_raw)
{
    __shared__ int s0[1024];
    __shared__ int s1[1024];
    __shared__ int is64_s;
    const int t = threadIdx.x;
    if (t == 0) {
        const int* ti = (const int*)targets_raw;
        int allz = 1;
        for (int i = 1; i < 128; i += 2) if (ti[i] != 0) { allz = 0; break; }
        is64_s = allz;
    }
    __syncthreads();
    const bool is64 = (is64_s != 0);

    int cls[8]; int c0 = 0, c1 = 0;
    #pragma unroll
    for (int i = 0; i < 8; i++) {
        const int idx = t * 8 + i;
        long long v = is64 ? ((const long long*)targets_raw)[idx]
                           : (long long)((const int*)targets_raw)[idx];
        int c = 0;
        if (v >= CUT1) c = 2; else if (v >= CUT0) c = 1;
        cls[i] = c;
        if (c == 1) c0++; else if (c == 2) c1++;
    }
    s0[t] = c0; s1[t] = c1;
    __syncthreads();
    for (int off = 1; off < 1024; off <<= 1) {
        int a0 = (t >= off) ? s0[t - off] : 0;
        int a1 = (t >= off) ? s1[t - off] : 0;
        __syncthreads();
        s0[t] += a0; s1[t] += a1;
        __syncthreads();
    }
    int b0 = s0[t] - c0, b1 = s1[t] - c1;
    #pragma unroll
    for (int i = 0; i < 8; i++) {
        const int idx = t * 8 + i;
        if (cls[i] == 1)      d_idx0[b0++] = idx;
        else if (cls[i] == 2) d_idx1[b1++] = idx;
    }
    if (t == 1023) {
        d_n0 = s0[1023];
        d_n1 = s1[1023];
        d_coff1 = (long long)s0[1023] * 18000LL;
    }
}

// -------------------- conversions --------------------
__global__ void tofp16_kernel(const float4* __restrict__ src,
                              __half2* __restrict__ dst, long long n4)
{
    long long i = blockIdx.x * (long long)blockDim.x + threadIdx.x;
    const long long stride = gridDim.x * (long long)blockDim.x;
    for (; i < n4; i += stride) {
        float4 v = src[i];
        dst[i*2+0] = __floats2half2_rn(v.x, v.y);
        dst[i*2+1] = __floats2half2_rn(v.z, v.w);
    }
}

// transposed fp32->fp16: dst[i][j] = fp16(src[j][i]), n x n
__global__ void trans16_kernel(const float* __restrict__ src,
                               __half* __restrict__ dst, int n)
{
    __shared__ __half t[32][33];
    const int bx = blockIdx.x * 32;
    const int by = blockIdx.y * 32;
    #pragma unroll
    for (int i = 0; i < 32; i += 8)
        t[threadIdx.y + i][threadIdx.x] =
            __float2half_rn(src[(long long)(by + threadIdx.y + i) * n + bx + threadIdx.x]);
    __syncthreads();
    #pragma unroll
    for (int i = 0; i < 32; i += 8)
        dst[(long long)(bx + threadIdx.y + i) * n + by + threadIdx.x] =
            t[threadIdx.x][threadIdx.y + i];
}

// head B: rows [0:2000) = embed, rows [2000:2002) = tailW
__global__ void pack_head16(const float* __restrict__ embed,
                            const float* __restrict__ tailW)
{
    const int row = blockIdx.x;
    const float* src = (row < CUT0) ? embed + (long long)row * HDIM
                                    : tailW + (long long)(row - CUT0) * HDIM;
    __half* dst = g_hb16 + (long long)row * HDIM;
    for (int i = threadIdx.x; i < HDIM; i += blockDim.x)
        dst[i] = __float2half_rn(src[i]);
}
__global__ void pack_head_bias(const float* __restrict__ sbias,
                               const float* __restrict__ tailb)
{
    const int i = blockIdx.x * blockDim.x + threadIdx.x;
    if (i < HEAD_NP)
        g_hbias[i] = (i < CUT0) ? sbias[i] : ((i < HEAD_N) ? tailb[i - CUT0] : 0.f);
}

// gather compacted hidden rows (fp16)
__global__ void gather16(const __half* __restrict__ h16,
                         const int* __restrict__ idx, const int* __restrict__ n,
                         __half* __restrict__ g)
{
    const int b = blockIdx.x;
    if (b >= *n) return;
    const int r = idx[b];
    const uint4* s = (const uint4*)(h16 + (long long)r * HDIM);
    uint4* d = (uint4*)(g + (long long)b * HDIM);
    for (int i = threadIdx.x; i < HDIM / 8; i += blockDim.x) d[i] = s[i];
}

// -------------------- host launch --------------------
extern "C" void kernel_launch(void* const* d_in, const int* in_sizes, int n_in,
                              void* d_out, int out_size)
{
    const float* hidden = (const float*)d_in[0];
    const float* embed  = (const float*)d_in[1];
    const float* tailW  = (const float*)d_in[2];
    const float* tailb  = (const float*)d_in[3];
    const float* sbias  = (const float*)d_in[4];
    const float* bias0  = (const float*)d_in[5];
    const float* bias1  = (const float*)d_in[6];
    const float* down0  = (const float*)d_in[7];
    const float* down1  = (const float*)d_in[8];
    const void*  targs  = d_in[9];
    float* out = (float*)d_out;

    #define SYM(p, s) void* p; cudaGetSymbolAddress(&p, s)
    SYM(p_h16, g_h16);   SYM(p_e16, g_e16);
    SYM(p_hb16, g_hb16); SYM(p_hbias, g_hbias);
    SYM(p_d0T, g_d0T);   SYM(p_T0, g_T0);
    SYM(p_d116, g_d116);
    SYM(p_g016, g_g016); SYM(p_g116, g_g116);
    SYM(p_dc1, g_dec1h);
    SYM(p_p0, g_p0h);    SYM(p_p1, g_p1h);
    SYM(p_i0, d_idx0);   SYM(p_i1, d_idx1);
    SYM(p_n0, d_n0);     SYM(p_n1, d_n1);   SYM(p_c1, d_coff1);
    #undef SYM

    cudaFuncSetAttribute(hgemm<0>, cudaFuncAttributeMaxDynamicSharedMemorySize, SMEM_BYTES);
    cudaFuncSetAttribute(hgemm<1>, cudaFuncAttributeMaxDynamicSharedMemorySize, SMEM_BYTES);

    // setup + conversions
    setup_kernel<<<1, 1024>>>(targs);
    tofp16_kernel<<<4096, 256>>>((const float4*)hidden, (__half2*)p_h16,
                                 (long long)BATCH * HDIM / 4);
    tofp16_kernel<<<16384, 256>>>((const float4*)(embed + (long long)CUT0 * HDIM),
                                  (__half2*)((__half*)p_e16 + (long long)CUT0 * HDIM),
                                  48000LL * HDIM / 4);
    trans16_kernel<<<dim3(32, 32), dim3(32, 8)>>>(down0, (__half*)p_d0T, HDIM);
    tofp16_kernel<<<256, 256>>>((const float4*)down1, (__half2*)p_d116,
                                256LL * HDIM / 4);
    pack_head16<<<HEAD_N, 256>>>(embed, tailW);
    pack_head_bias<<<8, 256>>>(sbias, tailb);
    gather16<<<BATCH, 128>>>((const __half*)p_h16, (const int*)p_i0,
                             (const int*)p_n0, (__half*)p_g016);
    gather16<<<BATCH, 128>>>((const __half*)p_h16, (const int*)p_i1,
                             (const int*)p_n1, (__half*)p_g116);

    #define H(p) (const __half*)(p)
    // T0 = down0^T @ down0  = d0T @ d0T^T   (1024 x 1024, K=1024)
    hgemm<1><<<dim3(8, 8), 128, SMEM_BYTES>>>(
        H(p_d0T), H(p_d0T), HDIM, HDIM, HDIM, nullptr,
        nullptr, nullptr, (long long)HDIM, nullptr, (__half*)p_T0);

    // head: [8192 x 2002] = hidden @ hb^T + hbias
    hgemm<0><<<dim3(16, 64), 128, SMEM_BYTES>>>(
        H(p_h16), H(p_hb16), HDIM, HEAD_N, BATCH, nullptr,
        out, (const float*)p_hbias, (long long)HEAD_N, nullptr, nullptr);

    // q0: [n0 x 1024] = hidden[idx0] @ T0  (T0 symmetric => NT ok)
    hgemm<1><<<dim3(8, 64), 128, SMEM_BYTES>>>(
        H(p_g016), H(p_T0), HDIM, HDIM, 0, (const int*)p_n0,
        nullptr, nullptr, (long long)HDIM, nullptr, (__half*)p_p0);

    // out0: [n0 x 18000] = q0 @ embed0^T + bias0  (B = fp16 embed rows)
    hgemm<0><<<dim3(141, 64), 128, SMEM_BYTES>>>(
        H(p_p0), H(p_e16) + (long long)CUT0 * HDIM,
        HDIM, DEC0_M, 0, (const int*)p_n0,
        out + HEAD_ELEMS, bias0, 18000LL, nullptr, nullptr);

    // dec1: [30000 x 256] = embed[20000:50000] @ down1^T -> fp16
    hgemm<1><<<dim3(2, 235), 128, SMEM_BYTES>>>(
        H(p_e16) + (long long)CUT1 * HDIM, H(p_d116),
        HDIM, 256, DEC1_M, nullptr,
        nullptr, nullptr, 256LL, nullptr, (__half*)p_dc1);

    // p1: [n1 x 256] = hidden[idx1] @ down1^T -> fp16
    hgemm<1><<<dim3(2, 64), 128, SMEM_BYTES>>>(
        H(p_g116), H(p_d116), HDIM, 256, 0, (const int*)p_n1,
        nullptr, nullptr, 256LL, nullptr, (__half*)p_p1);

    // out1: [n1 x 30000] = p1 @ dec1^T + bias1
    hgemm<0><<<dim3(235, 64), 128, SMEM_BYTES>>>(
        H(p_p1), H(p_dc1), 256, DEC1_M, 0, (const int*)p_n1,
        out + HEAD_ELEMS, bias1, 30000LL, (const long long*)p_c1, nullptr);
    #undef H
}

// round 8
// speedup vs baseline: 10.9144x; 1.1039x over previous
#include <cuda_runtime.h>
#include <cuda_bf16.h>
#include <cuda_fp16.h>
#include <cstdint>

// ---------------------------------------------------------------------------
// AdaptiveLogits, all GEMMs single-pass fp16 mma.sync (fp32 acc).
//   out0 = hidden0 @ (down0^T down0) @ embed0^T   (Gram restructure)
//   out1 = (hidden1 @ down1^T) @ (embed1 @ down1^T)^T
// 128x128x32 CTA tile, 4 warps @ 64x64, 4-stage cp.async pipeline.
// Graph-parallel: 3 chains forked onto 2 extra streams inside capture.
// ---------------------------------------------------------------------------

#define BATCH 8192
#define HDIM  1024
#define CUT0  2000
#define CUT1  20000
#define HEAD_N 2002
#define HEAD_NP 2048
#define HEAD_ELEMS (8192LL*2002LL)
#define DEC0_M 18000
#define DEC1_M 30000
#define DEC1_ROWS 30208
#define E_ROWS  50176

// -------------------- device scratch (zero-init; no allocs allowed) --------
__device__ __align__(256) __half g_h16  [BATCH*HDIM];
__device__ __align__(256) __half g_e16  [E_ROWS*HDIM];
__device__ __align__(256) __half g_hb16 [HEAD_NP*HDIM];
__device__ __align__(256) float  g_hbias[HEAD_NP];
__device__ __align__(256) __half g_d0T  [HDIM*HDIM];
__device__ __align__(256) __half g_T0   [HDIM*HDIM];
__device__ __align__(256) __half g_d116 [256*HDIM];
__device__ __align__(256) __half g_dec1h[DEC1_ROWS*256];
__device__ __align__(256) __half g_p0h  [BATCH*HDIM];
__device__ __align__(256) __half g_p1h  [BATCH*256];
__device__ int  d_idx0[BATCH];
__device__ int  d_idx1[BATCH];
__device__ int  d_n0;
__device__ int  d_n1;
__device__ long long d_coff1;

// -------------------- PTX helpers --------------------
__device__ __forceinline__ uint32_t smem_u32(const void* p) {
    return (uint32_t)__cvta_generic_to_shared(p);
}
__device__ __forceinline__ void cp16(uint32_t dst, const void* src) {
    asm volatile("cp.async.cg.shared.global [%0], [%1], 16;" :: "r"(dst), "l"(src) : "memory");
}
__device__ __forceinline__ void ldm4(uint32_t* r, uint32_t addr) {
    asm volatile("ldmatrix.sync.aligned.m8n8.x4.shared.b16 {%0,%1,%2,%3}, [%4];"
                 : "=r"(r[0]), "=r"(r[1]), "=r"(r[2]), "=r"(r[3]) : "r"(addr));
}
__device__ __forceinline__ void mma_f16(float* c, const uint32_t* a, const uint32_t* b) {
    asm volatile(
        "mma.sync.aligned.m16n8k16.row.col.f32.f16.f16.f32 "
        "{%0,%1,%2,%3}, {%4,%5,%6,%7}, {%8,%9}, {%0,%1,%2,%3};"
        : "+f"(c[0]), "+f"(c[1]), "+f"(c[2]), "+f"(c[3])
        : "r"(a[0]), "r"(a[1]), "r"(a[2]), "r"(a[3]), "r"(b[0]), "r"(b[1]));
}

// -------------------- tile geometry --------------------
#define ROWB 80
#define MAT_BYTES (128*ROWB)
#define ST_BYTES  (2*MAT_BYTES)
#define NSTAGE 4
#define SMEM_BYTES (NSTAGE*ST_BYTES)   // 81920

// per-thread fixed global row byte-offsets precomputed in the kernel
__device__ __forceinline__ void load_stage(
    uint32_t s, const char* Ah, const long long* aOff,
    const char* Bh, const long long* bOff, long long kByte, int tid)
{
    #pragma unroll
    for (int i = 0; i < 4; i++) {
        const int u = tid + i * 128;
        const int row = u >> 2;
        const int ch  = u & 3;
        const uint32_t d = (uint32_t)(row * ROWB + ch * 16);
        cp16(s + d,             Ah + aOff[i] + kByte + ch * 16);
        cp16(s + MAT_BYTES + d, Bh + bOff[i] + kByte + ch * 16);
    }
}

// -------------------- GEMM: C = A * B^T, fp16 in, fp32 acc -----------------
// OUTMODE 0: fp32 out (+bias, +*coff)   OUTMODE 1: fp16 out
// GATHER: A rows indirected through gidx
template <int OUTMODE, bool GATHER>
__global__ void __launch_bounds__(128, 2)
hgemm(const __half* __restrict__ Ah_, const __half* __restrict__ Bh_,
      const int* __restrict__ gidx,
      int K, int N, int Mstatic, const int* __restrict__ Mdev,
      float* __restrict__ Cf, const float* __restrict__ bias,
      long long cld, const long long* __restrict__ coff,
      __half* __restrict__ Ch)
{
    const int M = Mdev ? *Mdev : Mstatic;
    const int mBlk = blockIdx.y * 128;
    if (mBlk >= M) return;
    const int nBlk = blockIdx.x * 128;

    extern __shared__ __align__(1024) char smem[];
    const uint32_t sb = smem_u32(smem);
    const int tid = threadIdx.x;
    const int lane = tid & 31;
    const int wid = tid >> 5;
    const int wm = (wid & 1) * 64;
    const int wn = (wid >> 1) * 64;

    const char* Ah = (const char*)Ah_;
    const char* Bh = (const char*)Bh_;
    const long long aRB = (long long)K * 2;
    const long long bRB = (long long)K * 2;
    const int nk = K >> 5;

    // per-thread A/B row byte offsets (fixed across k-chunks)
    long long aOff[4], bOff[4];
    #pragma unroll
    for (int i = 0; i < 4; i++) {
        const int row = (tid + i * 128) >> 2;
        const long long ar = GATHER ? (long long)gidx[mBlk + row]
                                    : (long long)(mBlk + row);
        aOff[i] = ar * aRB;
        bOff[i] = (long long)(nBlk + row) * bRB;
    }

    float acc[4][8][4];
    #pragma unroll
    for (int i = 0; i < 4; i++)
        #pragma unroll
        for (int j = 0; j < 8; j++)
            #pragma unroll
            for (int k = 0; k < 4; k++) acc[i][j][k] = 0.f;

    const uint32_t aRowOff = (uint32_t)((wm + (lane & 15)) * ROWB);
    const uint32_t aColOff = (uint32_t)((lane >> 4) * 16);
    const uint32_t bRowOff = (uint32_t)((wn + ((lane >> 4) & 1) * 8 + (lane & 7)) * ROWB);
    const uint32_t bColOff = (uint32_t)(((lane >> 3) & 1) * 16);

    load_stage(sb, Ah, aOff, Bh, bOff, 0, tid);
    asm volatile("cp.async.commit_group;" ::: "memory");
    if (nk > 1) {
        load_stage(sb + ST_BYTES, Ah, aOff, Bh, bOff, 64, tid);
        asm volatile("cp.async.commit_group;" ::: "memory");
    }
    if (nk > 2) {
        load_stage(sb + 2 * ST_BYTES, Ah, aOff, Bh, bOff, 128, tid);
        asm volatile("cp.async.commit_group;" ::: "memory");
    }

    int stage = 0;
    for (int c = 0; c < nk; c++) {
        const int rem = nk - 1 - c;
        if (rem >= 2)
            asm volatile("cp.async.wait_group 2;" ::: "memory");
        else if (rem == 1)
            asm volatile("cp.async.wait_group 1;" ::: "memory");
        else
            asm volatile("cp.async.wait_group 0;" ::: "memory");
        __syncthreads();
        if (c + 3 < nk) {
            int ns = stage + 3; if (ns >= NSTAGE) ns -= NSTAGE;
            load_stage(sb + (uint32_t)ns * ST_BYTES, Ah, aOff, Bh, bOff,
                       (long long)(c + 3) * 64, tid);
            asm volatile("cp.async.commit_group;" ::: "memory");
        }
        const uint32_t st = sb + (uint32_t)stage * ST_BYTES;

        #pragma unroll
        for (int k16 = 0; k16 < 2; k16++) {
            uint32_t af[4][4], bf[4][4];
            const uint32_t ak = (uint32_t)(k16 * 32) + aColOff;
            const uint32_t bk = (uint32_t)(k16 * 32) + bColOff;
            #pragma unroll
            for (int mt = 0; mt < 4; mt++)
                ldm4(af[mt], st + aRowOff + (uint32_t)(mt * 16 * ROWB) + ak);
            #pragma unroll
            for (int g = 0; g < 4; g++)
                ldm4(bf[g], st + MAT_BYTES + bRowOff + (uint32_t)(g * 16 * ROWB) + bk);
            #pragma unroll
            for (int mt = 0; mt < 4; mt++)
                #pragma unroll
                for (int nt = 0; nt < 8; nt++)
                    mma_f16(acc[mt][nt], af[mt], &bf[nt >> 1][(nt & 1) * 2]);
        }
        if (++stage >= NSTAGE) stage = 0;
    }

    const long long cOff = (OUTMODE == 0 && coff) ? *coff : 0LL;
    const int r = lane >> 2;
    const int cq = (lane & 3) * 2;
    #pragma unroll
    for (int mt = 0; mt < 4; mt++) {
        #pragma unroll
        for (int nt = 0; nt < 8; nt++) {
            const int m0 = mBlk + wm + mt * 16 + r;
            const int n  = nBlk + wn + nt * 8 + cq;
            if (n >= N) continue;
            const float* a4 = acc[mt][nt];
            if (OUTMODE == 0) {
                const float b0 = bias[n], b1 = bias[n + 1];
                if (m0 < M)
                    *(float2*)(Cf + cOff + (long long)m0 * cld + n) =
                        make_float2(a4[0] + b0, a4[1] + b1);
                if (m0 + 8 < M)
                    *(float2*)(Cf + cOff + (long long)(m0 + 8) * cld + n) =
                        make_float2(a4[2] + b0, a4[3] + b1);
            } else {
                if (m0 < M)
                    *(__half2*)(Ch + (long long)m0 * cld + n) =
                        __floats2half2_rn(a4[0], a4[1]);
                if (m0 + 8 < M)
                    *(__half2*)(Ch + (long long)(m0 + 8) * cld + n) =
                        __floats2half2_rn(a4[2], a4[3]);
            }
        }
    }
}

// -------------------- setup: compaction --------------------
__global__ void setup_kernel(const void* __restrict__ targets_raw)
{
    __shared__ int s0[1024];
    __shared__ int s1[1024];
    __shared__ int is64_s;
    const int t = threadIdx.x;
    if (t == 0) {
        const int* ti = (const int*)targets_raw;
        int allz = 1;
        for (int i = 1; i < 128; i += 2) if (ti[i] != 0) { allz = 0; break; }
        is64_s = allz;
    }
    __syncthreads();
    const bool is64 = (is64_s != 0);

    int cls[8]; int c0 = 0, c1 = 0;
    #pragma unroll
    for (int i = 0; i < 8; i++) {
        const int idx = t * 8 + i;
        long long v = is64 ? ((const long long*)targets_raw)[idx]
                           : (long long)((const int*)targets_raw)[idx];
        int c = 0;
        if (v >= CUT1) c = 2; else if (v >= CUT0) c = 1;
        cls[i] = c;
        if (c == 1) c0++; else if (c == 2) c1++;
    }
    s0[t] = c0; s1[t] = c1;
    __syncthreads();
    for (int off = 1; off < 1024; off <<= 1) {
        int a0 = (t >= off) ? s0[t - off] : 0;
        int a1 = (t >= off) ? s1[t - off] : 0;
        __syncthreads();
        s0[t] += a0; s1[t] += a1;
        __syncthreads();
    }
    int b0 = s0[t] - c0, b1 = s1[t] - c1;
    #pragma unroll
    for (int i = 0; i < 8; i++) {
        const int idx = t * 8 + i;
        if (cls[i] == 1)      d_idx0[b0++] = idx;
        else if (cls[i] == 2) d_idx1[b1++] = idx;
    }
    if (t == 1023) {
        d_n0 = s0[1023];
        d_n1 = s1[1023];
        d_coff1 = (long long)s0[1023] * 18000LL;
    }
}

// -------------------- conversions --------------------
__global__ void tofp16_kernel(const float4* __restrict__ src,
                              __half2* __restrict__ dst, long long n4)
{
    long long i = blockIdx.x * (long long)blockDim.x + threadIdx.x;
    const long long stride = gridDim.x * (long long)blockDim.x;
    for (; i < n4; i += stride) {
        float4 v = src[i];
        dst[i*2+0] = __floats2half2_rn(v.x, v.y);
        dst[i*2+1] = __floats2half2_rn(v.z, v.w);
    }
}

__global__ void trans16_kernel(const float* __restrict__ src,
                               __half* __restrict__ dst, int n)
{
    __shared__ __half t[32][33];
    const int bx = blockIdx.x * 32;
    const int by = blockIdx.y * 32;
    #pragma unroll
    for (int i = 0; i < 32; i += 8)
        t[threadIdx.y + i][threadIdx.x] =
            __float2half_rn(src[(long long)(by + threadIdx.y + i) * n + bx + threadIdx.x]);
    __syncthreads();
    #pragma unroll
    for (int i = 0; i < 32; i += 8)
        dst[(long long)(bx + threadIdx.y + i) * n + by + threadIdx.x] =
            t[threadIdx.x][threadIdx.y + i];
}

__global__ void pack_head16(const float* __restrict__ embed,
                            const float* __restrict__ tailW)
{
    const int row = blockIdx.x;
    const float* src = (row < CUT0) ? embed + (long long)row * HDIM
                                    : tailW + (long long)(row - CUT0) * HDIM;
    __half* dst = g_hb16 + (long long)row * HDIM;
    for (int i = threadIdx.x; i < HDIM; i += blockDim.x)
        dst[i] = __float2half_rn(src[i]);
}
__global__ void pack_head_bias(const float* __restrict__ sbias,
                               const float* __restrict__ tailb)
{
    const int i = blockIdx.x * blockDim.x + threadIdx.x;
    if (i < HEAD_NP)
        g_hbias[i] = (i < CUT0) ? sbias[i] : ((i < HEAD_N) ? tailb[i - CUT0] : 0.f);
}

// -------------------- stream/event context (static init, pre-checkpoint) ---
namespace {
struct Ctx {
    cudaStream_t s1 = nullptr, s2 = nullptr;
    cudaEvent_t eF0 = nullptr, eF1 = nullptr, eJ1 = nullptr, eJ2 = nullptr;
    bool ok = false;
    Ctx() {
        ok = cudaStreamCreateWithFlags(&s1, cudaStreamNonBlocking) == cudaSuccess
          && cudaStreamCreateWithFlags(&s2, cudaStreamNonBlocking) == cudaSuccess
          && cudaEventCreateWithFlags(&eF0, cudaEventDisableTiming) == cudaSuccess
          && cudaEventCreateWithFlags(&eF1, cudaEventDisableTiming) == cudaSuccess
          && cudaEventCreateWithFlags(&eJ1, cudaEventDisableTiming) == cudaSuccess
          && cudaEventCreateWithFlags(&eJ2, cudaEventDisableTiming) == cudaSuccess;
    }
};
Ctx g_ctx;
}

// -------------------- host launch --------------------
extern "C" void kernel_launch(void* const* d_in, const int* in_sizes, int n_in,
                              void* d_out, int out_size)
{
    const float* hidden = (const float*)d_in[0];
    const float* embed  = (const float*)d_in[1];
    const float* tailW  = (const float*)d_in[2];
    const float* tailb  = (const float*)d_in[3];
    const float* sbias  = (const float*)d_in[4];
    const float* bias0  = (const float*)d_in[5];
    const float* bias1  = (const float*)d_in[6];
    const float* down0  = (const float*)d_in[7];
    const float* down1  = (const float*)d_in[8];
    const void*  targs  = d_in[9];
    float* out = (float*)d_out;

    #define SYM(p, s) void* p; cudaGetSymbolAddress(&p, s)
    SYM(p_h16, g_h16);   SYM(p_e16, g_e16);
    SYM(p_hb16, g_hb16); SYM(p_hbias, g_hbias);
    SYM(p_d0T, g_d0T);   SYM(p_T0, g_T0);
    SYM(p_d116, g_d116);
    SYM(p_dc1, g_dec1h);
    SYM(p_p0, g_p0h);    SYM(p_p1, g_p1h);
    SYM(p_i0, d_idx0);   SYM(p_i1, d_idx1);
    SYM(p_n0, d_n0);     SYM(p_n1, d_n1);   SYM(p_c1, d_coff1);
    #undef SYM

    cudaFuncSetAttribute(hgemm<0,false>, cudaFuncAttributeMaxDynamicSharedMemorySize, SMEM_BYTES);
    cudaFuncSetAttribute(hgemm<1,false>, cudaFuncAttributeMaxDynamicSharedMemorySize, SMEM_BYTES);
    cudaFuncSetAttribute(hgemm<1,true>,  cudaFuncAttributeMaxDynamicSharedMemorySize, SMEM_BYTES);

    const bool par = g_ctx.ok;
    cudaStream_t sA = par ? g_ctx.s1 : (cudaStream_t)0;
    cudaStream_t sB = par ? g_ctx.s2 : (cudaStream_t)0;

    // ---- common prep on stream 0 ----
    setup_kernel<<<1, 1024>>>(targs);
    tofp16_kernel<<<4096, 256>>>((const float4*)hidden, (__half2*)p_h16,
                                 (long long)BATCH * HDIM / 4);
    trans16_kernel<<<dim3(32, 32), dim3(32, 8)>>>(down0, (__half*)p_d0T, HDIM);
    tofp16_kernel<<<256, 256>>>((const float4*)down1, (__half2*)p_d116,
                                256LL * HDIM / 4);
    pack_head16<<<HEAD_N, 256>>>(embed, tailW);
    pack_head_bias<<<8, 256>>>(sbias, tailb);

    if (par) {
        cudaEventRecord(g_ctx.eF0, 0);
        cudaStreamWaitEvent(sA, g_ctx.eF0, 0);
        cudaStreamWaitEvent(sB, g_ctx.eF0, 0);
    }

    #define H(p) (const __half*)(p)
    // chain A prefix (sA): T0 = d0T @ d0T^T ; q0 = hidden[idx0] @ T0
    hgemm<1,false><<<dim3(8, 8), 128, SMEM_BYTES, sA>>>(
        H(p_d0T), H(p_d0T), nullptr, HDIM, HDIM, HDIM, nullptr,
        nullptr, nullptr, (long long)HDIM, nullptr, (__half*)p_T0);
    hgemm<1,true><<<dim3(8, 64), 128, SMEM_BYTES, sA>>>(
        H(p_h16), H(p_T0), (const int*)p_i0, HDIM, HDIM, 0, (const int*)p_n0,
        nullptr, nullptr, (long long)HDIM, nullptr, (__half*)p_p0);

    // chain B prefix (sB): p1 = hidden[idx1] @ down1^T
    hgemm<1,true><<<dim3(2, 64), 128, SMEM_BYTES, sB>>>(
        H(p_h16), H(p_d116), (const int*)p_i1, HDIM, 256, 0, (const int*)p_n1,
        nullptr, nullptr, 256LL, nullptr, (__half*)p_p1);

    // stream 0: big embed conversion, then head GEMM
    tofp16_kernel<<<16384, 256>>>((const float4*)(embed + (long long)CUT0 * HDIM),
                                  (__half2*)((__half*)p_e16 + (long long)CUT0 * HDIM),
                                  48000LL * HDIM / 4);
    if (par) {
        cudaEventRecord(g_ctx.eF1, 0);
        cudaStreamWaitEvent(sA, g_ctx.eF1, 0);
        cudaStreamWaitEvent(sB, g_ctx.eF1, 0);
    }
    hgemm<0,false><<<dim3(16, 64), 128, SMEM_BYTES>>>(
        H(p_h16), H(p_hb16), nullptr, HDIM, HEAD_N, BATCH, nullptr,
        out, (const float*)p_hbias, (long long)HEAD_N, nullptr, nullptr);

    // chain A (sA): out0 = q0 @ embed0^T + bias0
    hgemm<0,false><<<dim3(141, 64), 128, SMEM_BYTES, sA>>>(
        H(p_p0), H(p_e16) + (long long)CUT0 * HDIM, nullptr,
        HDIM, DEC0_M, 0, (const int*)p_n0,
        out + HEAD_ELEMS, bias0, 18000LL, nullptr, nullptr);

    // chain B (sB): dec1 = embed1 @ down1^T ; out1 = p1 @ dec1^T + bias1
    hgemm<1,false><<<dim3(2, 235), 128, SMEM_BYTES, sB>>>(
        H(p_e16) + (long long)CUT1 * HDIM, H(p_d116), nullptr,
        HDIM, 256, DEC1_M, nullptr,
        nullptr, nullptr, 256LL, nullptr, (__half*)p_dc1);
    hgemm<0,false><<<dim3(235, 64), 128, SMEM_BYTES, sB>>>(
        H(p_p1), H(p_dc1), nullptr, 256, DEC1_M, 0, (const int*)p_n1,
        out + HEAD_ELEMS, bias1, 30000LL, (const long long*)p_c1, nullptr);
    #undef H

    if (par) {
        cudaEventRecord(g_ctx.eJ1, sA);
        cudaEventRecord(g_ctx.eJ2, sB);
        cudaStreamWaitEvent((cudaStream_t)0, g_ctx.eJ1, 0);
        cudaStreamWaitEvent((cudaStream_t)0, g_ctx.eJ2, 0);
    }
}

// round 9
// speedup vs baseline: 11.1067x; 1.0176x over previous
#include <cuda_runtime.h>
#include <cuda_bf16.h>
#include <cuda_fp16.h>
#include <cstdint>

// ---------------------------------------------------------------------------
// AdaptiveLogits, all GEMMs single-pass fp16 mma.sync (fp32 acc).
//   out0 = hidden0 @ (down0^T down0) @ embed0^T   (Gram restructure)
//   out1 = (hidden1 @ down1^T) @ (embed1 @ down1^T)^T
// 128x128x32 CTA tile, 4 warps @ 64x64, 4-stage cp.async pipeline.
// Graph DAG: embed conversion hidden under head GEMM on a parallel branch.
// ---------------------------------------------------------------------------

#define BATCH 8192
#define HDIM  1024
#define CUT0  2000
#define CUT1  20000
#define HEAD_N 2002
#define HEAD_NP 2048
#define HEAD_ELEMS (8192LL*2002LL)
#define DEC0_M 18000
#define DEC1_M 30000
#define DEC1_ROWS 30208
#define E_ROWS  50176

// -------------------- device scratch (zero-init; no allocs allowed) --------
__device__ __align__(256) __half g_h16  [BATCH*HDIM];
__device__ __align__(256) __half g_e16  [E_ROWS*HDIM];
__device__ __align__(256) __half g_hb16 [HEAD_NP*HDIM];
__device__ __align__(256) float  g_hbias[HEAD_NP];
__device__ __align__(256) __half g_d0T  [HDIM*HDIM];
__device__ __align__(256) __half g_T0   [HDIM*HDIM];
__device__ __align__(256) __half g_d116 [256*HDIM];
__device__ __align__(256) __half g_dec1h[DEC1_ROWS*256];
__device__ __align__(256) __half g_p0h  [BATCH*HDIM];
__device__ __align__(256) __half g_p1h  [BATCH*256];
__device__ int  d_idx0[BATCH];
__device__ int  d_idx1[BATCH];
__device__ int  d_n0;
__device__ int  d_n1;
__device__ long long d_coff1;

// -------------------- PTX helpers --------------------
__device__ __forceinline__ uint32_t smem_u32(const void* p) {
    return (uint32_t)__cvta_generic_to_shared(p);
}
__device__ __forceinline__ void cp16(uint32_t dst, const void* src) {
    asm volatile("cp.async.cg.shared.global [%0], [%1], 16;" :: "r"(dst), "l"(src) : "memory");
}
__device__ __forceinline__ void ldm4(uint32_t* r, uint32_t addr) {
    asm volatile("ldmatrix.sync.aligned.m8n8.x4.shared.b16 {%0,%1,%2,%3}, [%4];"
                 : "=r"(r[0]), "=r"(r[1]), "=r"(r[2]), "=r"(r[3]) : "r"(addr));
}
__device__ __forceinline__ void mma_f16(float* c, const uint32_t* a, const uint32_t* b) {
    asm volatile(
        "mma.sync.aligned.m16n8k16.row.col.f32.f16.f16.f32 "
        "{%0,%1,%2,%3}, {%4,%5,%6,%7}, {%8,%9}, {%0,%1,%2,%3};"
        : "+f"(c[0]), "+f"(c[1]), "+f"(c[2]), "+f"(c[3])
        : "r"(a[0]), "r"(a[1]), "r"(a[2]), "r"(a[3]), "r"(b[0]), "r"(b[1]));
}

// -------------------- tile geometry --------------------
#define ROWB 80
#define MAT_BYTES (128*ROWB)
#define ST_BYTES  (2*MAT_BYTES)
#define NSTAGE 4
#define SMEM_BYTES (NSTAGE*ST_BYTES)   // 81920

__device__ __forceinline__ void load_stage(
    uint32_t s, const char* Ah, const long long* aOff,
    const char* Bh, const long long* bOff, long long kByte, int tid)
{
    #pragma unroll
    for (int i = 0; i < 4; i++) {
        const int u = tid + i * 128;
        const int row = u >> 2;
        const int ch  = u & 3;
        const uint32_t d = (uint32_t)(row * ROWB + ch * 16);
        cp16(s + d,             Ah + aOff[i] + kByte + ch * 16);
        cp16(s + MAT_BYTES + d, Bh + bOff[i] + kByte + ch * 16);
    }
}

// -------------------- GEMM: C = A * B^T, fp16 in, fp32 acc -----------------
template <int OUTMODE, bool GATHER>
__global__ void __launch_bounds__(128, 2)
hgemm(const __half* __restrict__ Ah_, const __half* __restrict__ Bh_,
      const int* __restrict__ gidx,
      int K, int N, int Mstatic, const int* __restrict__ Mdev,
      float* __restrict__ Cf, const float* __restrict__ bias,
      long long cld, const long long* __restrict__ coff,
      __half* __restrict__ Ch)
{
    const int M = Mdev ? *Mdev : Mstatic;
    const int mBlk = blockIdx.y * 128;
    if (mBlk >= M) return;
    const int nBlk = blockIdx.x * 128;

    extern __shared__ __align__(1024) char smem[];
    const uint32_t sb = smem_u32(smem);
    const int tid = threadIdx.x;
    const int lane = tid & 31;
    const int wid = tid >> 5;
    const int wm = (wid & 1) * 64;
    const int wn = (wid >> 1) * 64;

    const char* Ah = (const char*)Ah_;
    const char* Bh = (const char*)Bh_;
    const long long aRB = (long long)K * 2;
    const long long bRB = (long long)K * 2;
    const int nk = K >> 5;

    long long aOff[4], bOff[4];
    #pragma unroll
    for (int i = 0; i < 4; i++) {
        const int row = (tid + i * 128) >> 2;
        const long long ar = GATHER ? (long long)gidx[mBlk + row]
                                    : (long long)(mBlk + row);
        aOff[i] = ar * aRB;
        bOff[i] = (long long)(nBlk + row) * bRB;
    }

    float acc[4][8][4];
    #pragma unroll
    for (int i = 0; i < 4; i++)
        #pragma unroll
        for (int j = 0; j < 8; j++)
            #pragma unroll
            for (int k = 0; k < 4; k++) acc[i][j][k] = 0.f;

    const uint32_t aRowOff = (uint32_t)((wm + (lane & 15)) * ROWB);
    const uint32_t aColOff = (uint32_t)((lane >> 4) * 16);
    const uint32_t bRowOff = (uint32_t)((wn + ((lane >> 4) & 1) * 8 + (lane & 7)) * ROWB);
    const uint32_t bColOff = (uint32_t)(((lane >> 3) & 1) * 16);

    load_stage(sb, Ah, aOff, Bh, bOff, 0, tid);
    asm volatile("cp.async.commit_group;" ::: "memory");
    if (nk > 1) {
        load_stage(sb + ST_BYTES, Ah, aOff, Bh, bOff, 64, tid);
        asm volatile("cp.async.commit_group;" ::: "memory");
    }
    if (nk > 2) {
        load_stage(sb + 2 * ST_BYTES, Ah, aOff, Bh, bOff, 128, tid);
        asm volatile("cp.async.commit_group;" ::: "memory");
    }

    int stage = 0;
    for (int c = 0; c < nk; c++) {
        const int rem = nk - 1 - c;
        if (rem >= 2)
            asm volatile("cp.async.wait_group 2;" ::: "memory");
        else if (rem == 1)
            asm volatile("cp.async.wait_group 1;" ::: "memory");
        else
            asm volatile("cp.async.wait_group 0;" ::: "memory");
        __syncthreads();
        if (c + 3 < nk) {
            int ns = stage + 3; if (ns >= NSTAGE) ns -= NSTAGE;
            load_stage(sb + (uint32_t)ns * ST_BYTES, Ah, aOff, Bh, bOff,
                       (long long)(c + 3) * 64, tid);
            asm volatile("cp.async.commit_group;" ::: "memory");
        }
        const uint32_t st = sb + (uint32_t)stage * ST_BYTES;

        #pragma unroll
        for (int k16 = 0; k16 < 2; k16++) {
            uint32_t af[4][4], bf[4][4];
            const uint32_t ak = (uint32_t)(k16 * 32) + aColOff;
            const uint32_t bk = (uint32_t)(k16 * 32) + bColOff;
            #pragma unroll
            for (int mt = 0; mt < 4; mt++)
                ldm4(af[mt], st + aRowOff + (uint32_t)(mt * 16 * ROWB) + ak);
            #pragma unroll
            for (int g = 0; g < 4; g++)
                ldm4(bf[g], st + MAT_BYTES + bRowOff + (uint32_t)(g * 16 * ROWB) + bk);
            #pragma unroll
            for (int mt = 0; mt < 4; mt++)
                #pragma unroll
                for (int nt = 0; nt < 8; nt++)
                    mma_f16(acc[mt][nt], af[mt], &bf[nt >> 1][(nt & 1) * 2]);
        }
        if (++stage >= NSTAGE) stage = 0;
    }

    const long long cOff = (OUTMODE == 0 && coff) ? *coff : 0LL;
    const int r = lane >> 2;
    const int cq = (lane & 3) * 2;
    #pragma unroll
    for (int mt = 0; mt < 4; mt++) {
        #pragma unroll
        for (int nt = 0; nt < 8; nt++) {
            const int m0 = mBlk + wm + mt * 16 + r;
            const int n  = nBlk + wn + nt * 8 + cq;
            if (n >= N) continue;
            const float* a4 = acc[mt][nt];
            if (OUTMODE == 0) {
                const float b0 = bias[n], b1 = bias[n + 1];
                if (m0 < M)
                    *(float2*)(Cf + cOff + (long long)m0 * cld + n) =
                        make_float2(a4[0] + b0, a4[1] + b1);
                if (m0 + 8 < M)
                    *(float2*)(Cf + cOff + (long long)(m0 + 8) * cld + n) =
                        make_float2(a4[2] + b0, a4[3] + b1);
            } else {
                if (m0 < M)
                    *(__half2*)(Ch + (long long)m0 * cld + n) =
                        __floats2half2_rn(a4[0], a4[1]);
                if (m0 + 8 < M)
                    *(__half2*)(Ch + (long long)(m0 + 8) * cld + n) =
                        __floats2half2_rn(a4[2], a4[3]);
            }
        }
    }
}

// -------------------- setup: compaction --------------------
__global__ void setup_kernel(const void* __restrict__ targets_raw)
{
    __shared__ int s0[1024];
    __shared__ int s1[1024];
    __shared__ int is64_s;
    const int t = threadIdx.x;
    if (t == 0) {
        const int* ti = (const int*)targets_raw;
        int allz = 1;
        for (int i = 1; i < 128; i += 2) if (ti[i] != 0) { allz = 0; break; }
        is64_s = allz;
    }
    __syncthreads();
    const bool is64 = (is64_s != 0);

    int cls[8]; int c0 = 0, c1 = 0;
    #pragma unroll
    for (int i = 0; i < 8; i++) {
        const int idx = t * 8 + i;
        long long v = is64 ? ((const long long*)targets_raw)[idx]
                           : (long long)((const int*)targets_raw)[idx];
        int c = 0;
        if (v >= CUT1) c = 2; else if (v >= CUT0) c = 1;
        cls[i] = c;
        if (c == 1) c0++; else if (c == 2) c1++;
    }
    s0[t] = c0; s1[t] = c1;
    __syncthreads();
    for (int off = 1; off < 1024; off <<= 1) {
        int a0 = (t >= off) ? s0[t - off] : 0;
        int a1 = (t >= off) ? s1[t - off] : 0;
        __syncthreads();
        s0[t] += a0; s1[t] += a1;
        __syncthreads();
    }
    int b0 = s0[t] - c0, b1 = s1[t] - c1;
    #pragma unroll
    for (int i = 0; i < 8; i++) {
        const int idx = t * 8 + i;
        if (cls[i] == 1)      d_idx0[b0++] = idx;
        else if (cls[i] == 2) d_idx1[b1++] = idx;
    }
    if (t == 1023) {
        d_n0 = s0[1023];
        d_n1 = s1[1023];
        d_coff1 = (long long)s0[1023] * 18000LL;
    }
}

// -------------------- conversions --------------------
__global__ void tofp16_kernel(const float4* __restrict__ src,
                              __half2* __restrict__ dst, long long n4)
{
    long long i = blockIdx.x * (long long)blockDim.x + threadIdx.x;
    const long long stride = gridDim.x * (long long)blockDim.x;
    for (; i < n4; i += stride) {
        float4 v = src[i];
        dst[i*2+0] = __floats2half2_rn(v.x, v.y);
        dst[i*2+1] = __floats2half2_rn(v.z, v.w);
    }
}

__global__ void trans16_kernel(const float* __restrict__ src,
                               __half* __restrict__ dst, int n)
{
    __shared__ __half t[32][33];
    const int bx = blockIdx.x * 32;
    const int by = blockIdx.y * 32;
    #pragma unroll
    for (int i = 0; i < 32; i += 8)
        t[threadIdx.y + i][threadIdx.x] =
            __float2half_rn(src[(long long)(by + threadIdx.y + i) * n + bx + threadIdx.x]);
    __syncthreads();
    #pragma unroll
    for (int i = 0; i < 32; i += 8)
        dst[(long long)(bx + threadIdx.y + i) * n + by + threadIdx.x] =
            t[threadIdx.x][threadIdx.y + i];
}

__global__ void pack_head16(const float* __restrict__ embed,
                            const float* __restrict__ tailW)
{
    const int row = blockIdx.x;
    const float* src = (row < CUT0) ? embed + (long long)row * HDIM
                                    : tailW + (long long)(row - CUT0) * HDIM;
    __half* dst = g_hb16 + (long long)row * HDIM;
    for (int i = threadIdx.x; i < HDIM; i += blockDim.x)
        dst[i] = __float2half_rn(src[i]);
}
__global__ void pack_head_bias(const float* __restrict__ sbias,
                               const float* __restrict__ tailb)
{
    const int i = blockIdx.x * blockDim.x + threadIdx.x;
    if (i < HEAD_NP)
        g_hbias[i] = (i < CUT0) ? sbias[i] : ((i < HEAD_N) ? tailb[i - CUT0] : 0.f);
}

// -------------------- stream/event context (static init, pre-checkpoint) ---
namespace {
struct Ctx {
    cudaStream_t s1 = nullptr, s2 = nullptr;
    cudaEvent_t eS = nullptr, eH = nullptr, eC = nullptr,
                eJ1 = nullptr, eJ2 = nullptr;
    bool ok = false;
    Ctx() {
        ok = cudaStreamCreateWithFlags(&s1, cudaStreamNonBlocking) == cudaSuccess
          && cudaStreamCreateWithFlags(&s2, cudaStreamNonBlocking) == cudaSuccess
          && cudaEventCreateWithFlags(&eS,  cudaEventDisableTiming) == cudaSuccess
          && cudaEventCreateWithFlags(&eH,  cudaEventDisableTiming) == cudaSuccess
          && cudaEventCreateWithFlags(&eC,  cudaEventDisableTiming) == cudaSuccess
          && cudaEventCreateWithFlags(&eJ1, cudaEventDisableTiming) == cudaSuccess
          && cudaEventCreateWithFlags(&eJ2, cudaEventDisableTiming) == cudaSuccess;
    }
};
Ctx g_ctx;
}

// -------------------- host launch --------------------
extern "C" void kernel_launch(void* const* d_in, const int* in_sizes, int n_in,
                              void* d_out, int out_size)
{
    const float* hidden = (const float*)d_in[0];
    const float* embed  = (const float*)d_in[1];
    const float* tailW  = (const float*)d_in[2];
    const float* tailb  = (const float*)d_in[3];
    const float* sbias  = (const float*)d_in[4];
    const float* bias0  = (const float*)d_in[5];
    const float* bias1  = (const float*)d_in[6];
    const float* down0  = (const float*)d_in[7];
    const float* down1  = (const float*)d_in[8];
    const void*  targs  = d_in[9];
    float* out = (float*)d_out;

    #define SYM(p, s) void* p; cudaGetSymbolAddress(&p, s)
    SYM(p_h16, g_h16);   SYM(p_e16, g_e16);
    SYM(p_hb16, g_hb16); SYM(p_hbias, g_hbias);
    SYM(p_d0T, g_d0T);   SYM(p_T0, g_T0);
    SYM(p_d116, g_d116);
    SYM(p_dc1, g_dec1h);
    SYM(p_p0, g_p0h);    SYM(p_p1, g_p1h);
    SYM(p_i0, d_idx0);   SYM(p_i1, d_idx1);
    SYM(p_n0, d_n0);     SYM(p_n1, d_n1);   SYM(p_c1, d_coff1);
    #undef SYM

    cudaFuncSetAttribute(hgemm<0,false>, cudaFuncAttributeMaxDynamicSharedMemorySize, SMEM_BYTES);
    cudaFuncSetAttribute(hgemm<1,false>, cudaFuncAttributeMaxDynamicSharedMemorySize, SMEM_BYTES);
    cudaFuncSetAttribute(hgemm<1,true>,  cudaFuncAttributeMaxDynamicSharedMemorySize, SMEM_BYTES);

    const bool par = g_ctx.ok;
    cudaStream_t sA = par ? g_ctx.s1 : (cudaStream_t)0;
    cudaStream_t sB = par ? g_ctx.s2 : (cudaStream_t)0;

    #define H(p) (const __half*)(p)

    // fork point (no prior work needed for sA/sB prep kernels)
    if (par) {
        cudaEventRecord(g_ctx.eS, 0);
        cudaStreamWaitEvent(sA, g_ctx.eS, 0);
        cudaStreamWaitEvent(sB, g_ctx.eS, 0);
    }

    // ---- s0: setup + hidden conversion + head packs -> eH -> head GEMM ----
    setup_kernel<<<1, 1024>>>(targs);
    tofp16_kernel<<<4096, 256>>>((const float4*)hidden, (__half2*)p_h16,
                                 (long long)BATCH * HDIM / 4);
    pack_head16<<<HEAD_N, 256>>>(embed, tailW);
    pack_head_bias<<<8, 256>>>(sbias, tailb);
    if (par) cudaEventRecord(g_ctx.eH, 0);

    // head: [8192 x 2002] = hidden @ hb^T + hbias   (starts early)
    hgemm<0,false><<<dim3(16, 64), 128, SMEM_BYTES>>>(
        H(p_h16), H(p_hb16), nullptr, HDIM, HEAD_N, BATCH, nullptr,
        out, (const float*)p_hbias, (long long)HEAD_N, nullptr, nullptr);

    // ---- sA: trans16 -> T0 -> (eH) q0 -> (eC) out0 ----
    trans16_kernel<<<dim3(32, 32), dim3(32, 8), 0, sA>>>(down0, (__half*)p_d0T, HDIM);
    hgemm<1,false><<<dim3(8, 8), 128, SMEM_BYTES, sA>>>(
        H(p_d0T), H(p_d0T), nullptr, HDIM, HDIM, HDIM, nullptr,
        nullptr, nullptr, (long long)HDIM, nullptr, (__half*)p_T0);
    if (par) cudaStreamWaitEvent(sA, g_ctx.eH, 0);
    hgemm<1,true><<<dim3(8, 64), 128, SMEM_BYTES, sA>>>(
        H(p_h16), H(p_T0), (const int*)p_i0, HDIM, HDIM, 0, (const int*)p_n0,
        nullptr, nullptr, (long long)HDIM, nullptr, (__half*)p_p0);

    // ---- sB: down1 conv -> embed conv -> eC -> (eH) p1 -> dec1 -> out1 ----
    tofp16_kernel<<<256, 256, 0, sB>>>((const float4*)down1, (__half2*)p_d116,
                                       256LL * HDIM / 4);
    tofp16_kernel<<<16384, 256, 0, sB>>>(
        (const float4*)(embed + (long long)CUT0 * HDIM),
        (__half2*)((__half*)p_e16 + (long long)CUT0 * HDIM),
        48000LL * HDIM / 4);
    if (par) {
        cudaEventRecord(g_ctx.eC, sB);
        cudaStreamWaitEvent(sB, g_ctx.eH, 0);
    }
    hgemm<1,true><<<dim3(2, 64), 128, SMEM_BYTES, sB>>>(
        H(p_h16), H(p_d116), (const int*)p_i1, HDIM, 256, 0, (const int*)p_n1,
        nullptr, nullptr, 256LL, nullptr, (__half*)p_p1);
    hgemm<1,false><<<dim3(2, 235), 128, SMEM_BYTES, sB>>>(
        H(p_e16) + (long long)CUT1 * HDIM, H(p_d116), nullptr,
        HDIM, 256, DEC1_M, nullptr,
        nullptr, nullptr, 256LL, nullptr, (__half*)p_dc1);

    // ---- sA: out0 = q0 @ embed0^T + bias0 (needs eC) ----
    if (par) cudaStreamWaitEvent(sA, g_ctx.eC, 0);
    hgemm<0,false><<<dim3(141, 64), 128, SMEM_BYTES, sA>>>(
        H(p_p0), H(p_e16) + (long long)CUT0 * HDIM, nullptr,
        HDIM, DEC0_M, 0, (const int*)p_n0,
        out + HEAD_ELEMS, bias0, 18000LL, nullptr, nullptr);

    // ---- sB: out1 = p1 @ dec1^T + bias1 ----
    hgemm<0,false><<<dim3(235, 64), 128, SMEM_BYTES, sB>>>(
        H(p_p1), H(p_dc1), nullptr, 256, DEC1_M, 0, (const int*)p_n1,
        out + HEAD_ELEMS, bias1, 30000LL, (const long long*)p_c1, nullptr);
    #undef H

    if (par) {
        cudaEventRecord(g_ctx.eJ1, sA);
        cudaEventRecord(g_ctx.eJ2, sB);
        cudaStreamWaitEvent((cudaStream_t)0, g_ctx.eJ1, 0);
        cudaStreamWaitEvent((cudaStream_t)0, g_ctx.eJ2, 0);
    }
}